// round 14
// baseline (speedup 1.0000x reference)
#include <cuda_runtime.h>
#include <cuda_fp16.h>
#include <math.h>
#include <stdint.h>

#define BB 256
#define NN 180
#define CC 768
#define RR 192
#define MM (BB*NN)     // 46080
#define NCHUNK (CC/64) // 12 K-chunks of 64 halfs (128B)

// ---------------- scratch (static device allocations) ----------------
__device__ __half g_xh[(size_t)MM * CC];       // fp16 copy of x
__device__ __half g_Wqkth[384 * 768];          // [n][k] fp16 Wq^T | Wk^T
__device__ __half g_Wgth[768 * 768];           // [n][k] fp16 Wg^T
__device__ __half g_QKh[(size_t)MM * 384];     // [M, 384] Q|K fp16
__device__ float  g_S[(size_t)BB * NN * NN];   // raw scores f32
__device__ __half g_Sh[(size_t)BB * NN * 192]; // A_comb fp16, rows padded to 192
__device__ __half g_Zh[(size_t)MM * CC];       // A_comb @ x, fp16
__device__ __half g_Hh[(size_t)MM * CC];       // pre-LN h, fp16

// ---------------- helpers ----------------
__device__ __forceinline__ uint32_t smem_u32(const void* p) {
    uint32_t a;
    asm("{ .reg .u64 t; cvta.to.shared.u64 t, %1; cvt.u32.u64 %0, t; }" : "=r"(a) : "l"(p));
    return a;
}
// 128-byte swizzle on byte offsets (rows are 128B)
#define SWZB(o) ((o) ^ (((o) >> 3) & 0x70))

__device__ __forceinline__ void cp16(uint32_t dst, const void* src) {
    asm volatile("cp.async.ca.shared.global [%0], [%1], 16;"
                 :: "r"(dst), "l"(src) : "memory");
}
#define CP_COMMIT() asm volatile("cp.async.commit_group;" ::: "memory")
#define CP_WAIT1()  asm volatile("cp.async.wait_group 1;" ::: "memory")
#define CP_WAIT0()  asm volatile("cp.async.wait_group 0;" ::: "memory")

__device__ __forceinline__ void ldsm_x4(uint32_t* r, uint32_t addr) {
    asm volatile("ldmatrix.sync.aligned.m8n8.x4.shared.b16 {%0,%1,%2,%3}, [%4];"
                 : "=r"(r[0]), "=r"(r[1]), "=r"(r[2]), "=r"(r[3]) : "r"(addr));
}

__device__ __forceinline__ void mma_f16(float* c, const uint32_t* a, const uint32_t* b) {
    asm volatile(
        "mma.sync.aligned.m16n8k16.row.col.f32.f16.f16.f32 "
        "{%0,%1,%2,%3}, {%4,%5,%6,%7}, {%8,%9}, {%0,%1,%2,%3};"
        : "+f"(c[0]), "+f"(c[1]), "+f"(c[2]), "+f"(c[3])
        : "r"(a[0]), "r"(a[1]), "r"(a[2]), "r"(a[3]), "r"(b[0]), "r"(b[1]));
}

// A fragment via ldmatrix.x4: rows base_r..base_r+15, k bytes kb..kb+31
__device__ __forceinline__ void ld_afrag(uint32_t* afr, uint32_t Asu,
                                         int base_r, int kb, int lane) {
    const int row = base_r + (lane & 15);
    ldsm_x4(afr, Asu + SWZB(row * 128 + kb + ((lane >> 4) << 4)));
}
// B fragment pair via ldmatrix.x4: n rows base_n..+15 (two n8 blocks), k bytes kb..kb+31
__device__ __forceinline__ void ld_bfrag2(uint32_t* b4, uint32_t Bsu,
                                          int base_n, int kb, int lane) {
    const int n = base_n + ((lane >> 4) << 3) + (lane & 7);
    const int koff = kb + (((lane >> 3) & 1) << 4);
    ldsm_x4(b4, Bsu + SWZB(n * 128 + koff));
}

// ================== main GEMM: Out[M,NC] = A[M,768]h @ Wt[NC,768]h^T ==================
// Tile 128x128xK64, 256 threads (8 warps = 4m x 2n), 2-stage cp.async, 1 sync/chunk.
template<int NC, bool RELU, bool SPLITB>
__global__ void __launch_bounds__(256, 2) gemm_h(
    const __half* __restrict__ A,
    const __half* __restrict__ Wt,
    const float* __restrict__ bias0,
    const float* __restrict__ bias1,
    const __half* __restrict__ residh,
    __half* __restrict__ OutH)
{
    extern __shared__ char smc[];     // 2 stages x (A 16KB + B 16KB)
    const uint32_t sbase = smem_u32(smc);
    const int tid  = threadIdx.x;
    const int lane = tid & 31;
    const int wid  = tid >> 5;
    const int wm   = wid & 3;
    const int wn   = wid >> 2;
    const int lr   = lane >> 2;
    const int lc   = lane & 3;
    const int bm   = blockIdx.y * 128;
    const int bn   = blockIdx.x * 128;

    float acc[2][8][4];
    #pragma unroll
    for (int i = 0; i < 2; i++)
        #pragma unroll
        for (int j = 0; j < 8; j++)
            #pragma unroll
            for (int k = 0; k < 4; k++) acc[i][j][k] = 0.f;

    const int lrow = tid >> 3;
    const int lc4  = tid & 7;

    auto issue_load = [&](int c, int s) {
        const uint32_t abase = sbase + (uint32_t)s * 32768u;
        const uint32_t bbase = abase + 16384u;
        const int k0 = c * 64;
        #pragma unroll
        for (int i = 0; i < 4; i++) {
            const int row = lrow + i * 32;
            const uint32_t soff = SWZB(row * 128 + lc4 * 16);
            cp16(abase + soff, A  + (size_t)(bm + row) * CC + k0 + lc4 * 8);
            cp16(bbase + soff, Wt + (size_t)(bn + row) * CC + k0 + lc4 * 8);
        }
        CP_COMMIT();
    };

    issue_load(0, 0);

    #pragma unroll 1
    for (int c = 0; c < NCHUNK; c++) {
        CP_WAIT0();
        __syncthreads();
        if (c + 1 < NCHUNK) issue_load(c + 1, (c + 1) & 1);

        const uint32_t Asu = sbase + (uint32_t)(c & 1) * 32768u;
        const uint32_t Bsu = Asu + 16384u;

        #pragma unroll
        for (int ks = 0; ks < 4; ks++) {
            const int kb = ks * 32;
            uint32_t afr[2][4];
            #pragma unroll
            for (int fm = 0; fm < 2; fm++)
                ld_afrag(afr[fm], Asu, wm * 32 + fm * 16, kb, lane);
            uint32_t bfr[4][4];
            #pragma unroll
            for (int fp = 0; fp < 4; fp++)
                ld_bfrag2(bfr[fp], Bsu, wn * 64 + fp * 16, kb, lane);
            #pragma unroll
            for (int fm = 0; fm < 2; fm++)
                #pragma unroll
                for (int fp = 0; fp < 4; fp++) {
                    mma_f16(acc[fm][fp * 2 + 0], afr[fm], &bfr[fp][0]);
                    mma_f16(acc[fm][fp * 2 + 1], afr[fm], &bfr[fp][2]);
                }
        }
    }

    // ---- epilogue ----
    #pragma unroll
    for (int fm = 0; fm < 2; fm++) {
        #pragma unroll
        for (int h = 0; h < 2; h++) {
            const int m = bm + wm * 32 + fm * 16 + lr + h * 8;
            #pragma unroll
            for (int fn = 0; fn < 8; fn++) {
                const int n = bn + wn * 64 + fn * 8 + lc * 2;
                float b0, b1;
                if (SPLITB) {
                    b0 = (n < RR) ? bias0[n] : bias1[n - RR];
                    b1 = (n + 1 < RR) ? bias0[n + 1] : bias1[n + 1 - RR];
                } else {
                    b0 = bias0[n]; b1 = bias0[n + 1];
                }
                float vx = acc[fm][fn][h * 2 + 0] + b0;
                float vy = acc[fm][fn][h * 2 + 1] + b1;
                if (RELU) {
                    const float2 rx = __half22float2(
                        *(const half2*)(residh + (size_t)m * NC + n));
                    vx = fmaxf(vx, 0.f) + rx.x;
                    vy = fmaxf(vy, 0.f) + rx.y;
                }
                *(half2*)(OutH + (size_t)m * NC + n) = __floats2half2_rn(vx, vy);
            }
        }
    }
}

// ================== scores = Q @ K^T / sqrt(R) (fp16 tensor, batched) ==================
// Per batch: M=192 (180 valid), N=96, K=192 (3 chunks of 64). grid (2, 256).
__global__ void __launch_bounds__(256, 1) scores_h() {
    __shared__ __align__(128) char As[192 * 128];   // Q tile [192][64h]
    __shared__ __align__(128) char Bs[96 * 128];    // K tile [96][64h]
    const int tid = threadIdx.x;
    const int wid = tid >> 5, lane = tid & 31;
    const int wm = wid & 3, wn = wid >> 2;
    const int lr = lane >> 2, lc = lane & 3;
    const int b  = blockIdx.y;
    const int bn = blockIdx.x * 96;
    const __half* qb = g_QKh + (size_t)b * NN * 384;
    const uint32_t Asu = smem_u32(As), Bsu = smem_u32(Bs);

    float acc[3][6][4];
    #pragma unroll
    for (int i = 0; i < 3; i++)
        #pragma unroll
        for (int j = 0; j < 6; j++)
            #pragma unroll
            for (int k = 0; k < 4; k++) acc[i][j][k] = 0.f;

    uint4 ar[6], br[3];
    auto gload = [&](int c) {
        const int k0 = c * 64;
        #pragma unroll
        for (int i = 0; i < 6; i++) {
            const int idx = tid + i * 256;
            const int row = idx >> 3, c4 = idx & 7;
            uint4 v = make_uint4(0, 0, 0, 0);
            if (row < NN) v = *(const uint4*)(qb + (size_t)row * 384 + k0 + c4 * 8);
            ar[i] = v;
        }
        #pragma unroll
        for (int i = 0; i < 3; i++) {
            const int idx = tid + i * 256;
            const int row = idx >> 3, c4 = idx & 7;
            uint4 v = make_uint4(0, 0, 0, 0);
            if (bn + row < NN) v = *(const uint4*)(qb + (size_t)(bn + row) * 384 + 192 + k0 + c4 * 8);
            br[i] = v;
        }
    };
    auto sstore = [&]() {
        #pragma unroll
        for (int i = 0; i < 6; i++) {
            const int idx = tid + i * 256;
            const int row = idx >> 3, c4 = idx & 7;
            *(uint4*)(As + SWZB(row * 128 + c4 * 16)) = ar[i];
        }
        #pragma unroll
        for (int i = 0; i < 3; i++) {
            const int idx = tid + i * 256;
            const int row = idx >> 3, c4 = idx & 7;
            *(uint4*)(Bs + SWZB(row * 128 + c4 * 16)) = br[i];
        }
    };

    gload(0);
    #pragma unroll 1
    for (int c = 0; c < 3; c++) {
        sstore();
        if (c < 2) gload(c + 1);
        __syncthreads();
        #pragma unroll
        for (int ks = 0; ks < 4; ks++) {
            const int kb = ks * 32;
            uint32_t afr[3][4];
            #pragma unroll
            for (int fm = 0; fm < 3; fm++)
                ld_afrag(afr[fm], Asu, wm * 48 + fm * 16, kb, lane);
            uint32_t bfr[3][4];
            #pragma unroll
            for (int fp = 0; fp < 3; fp++)
                ld_bfrag2(bfr[fp], Bsu, wn * 48 + fp * 16, kb, lane);
            #pragma unroll
            for (int fm = 0; fm < 3; fm++)
                #pragma unroll
                for (int fp = 0; fp < 3; fp++) {
                    mma_f16(acc[fm][fp * 2 + 0], afr[fm], &bfr[fp][0]);
                    mma_f16(acc[fm][fp * 2 + 1], afr[fm], &bfr[fp][2]);
                }
        }
        __syncthreads();
    }

    const float scale = 0.07216878364870323f;   // 1/sqrt(192)
    float* Sb = g_S + (size_t)b * NN * NN;
    #pragma unroll
    for (int fm = 0; fm < 3; fm++) {
        #pragma unroll
        for (int h = 0; h < 2; h++) {
            const int m = wm * 48 + fm * 16 + lr + h * 8;
            if (m < NN) {
                #pragma unroll
                for (int fn = 0; fn < 6; fn++) {
                    const int n = bn + wn * 48 + fn * 8 + lc * 2;
                    if (n < NN)     Sb[(size_t)m * NN + n]     = acc[fm][fn][h * 2 + 0] * scale;
                    if (n + 1 < NN) Sb[(size_t)m * NN + n + 1] = acc[fm][fn][h * 2 + 1] * scale;
                }
            }
        }
    }
}

// ================== z = A_comb @ x (fp16 tensor, batched) ==================
// Split-M: per block M=96 (half of 192-pad), N=128 channels, K=192 tokens.
// grid (6, 2, 256). 8 warps = 2m x 4n (warp tile 48x32), acc 48 floats -> 2 CTAs/SM.
__global__ void __launch_bounds__(256, 2) aggregate_h() {
    __shared__ __align__(128) char As[96 * 128];    // A_comb half-tile [96 rows][64 tok]
    __shared__ __align__(128) char Bs[128 * 128];   // x^T [128 ch][64 tok]
    const int tid = threadIdx.x;
    const int wid = tid >> 5, lane = tid & 31;
    const int wm = wid & 1, wn = wid >> 1;
    const int lr = lane >> 2, lc = lane & 3;
    const int bc = blockIdx.x * 128;
    const int m0 = blockIdx.y * 96;
    const int b  = blockIdx.z;
    const __half* Sb = g_Sh + (size_t)b * NN * 192;
    const __half* xb = g_xh + (size_t)b * NN * CC;
    const uint32_t Asu = smem_u32(As), Bsu = smem_u32(Bs);

    float acc[3][4][4];
    #pragma unroll
    for (int i = 0; i < 3; i++)
        #pragma unroll
        for (int j = 0; j < 4; j++)
            #pragma unroll
            for (int k = 0; k < 4; k++) acc[i][j][k] = 0.f;

    uint4 ar[3], bra[2], brb[2];
    auto gload = [&](int c) {
        const int k0 = c * 64;
        #pragma unroll
        for (int i = 0; i < 3; i++) {            // A: 96 rows x 8 units
            const int idx = tid + i * 256;
            const int row = idx >> 3, c4 = idx & 7;
            uint4 v = make_uint4(0, 0, 0, 0);
            if (m0 + row < NN) v = *(const uint4*)(Sb + (size_t)(m0 + row) * 192 + k0 + c4 * 8);
            ar[i] = v;
        }
        #pragma unroll
        for (int i = 0; i < 2; i++) {
            const int task = tid + i * 256;
            const int tp = task & 31, chg = task >> 5;
            const int tokA = k0 + 2 * tp, tokB = tokA + 1;
            uint4 va = make_uint4(0, 0, 0, 0), vb = make_uint4(0, 0, 0, 0);
            if (tokA < NN) va = *(const uint4*)(xb + (size_t)tokA * CC + bc + chg * 8);
            if (tokB < NN) vb = *(const uint4*)(xb + (size_t)tokB * CC + bc + chg * 8);
            bra[i] = va; brb[i] = vb;
        }
    };
    auto sstore = [&]() {
        #pragma unroll
        for (int i = 0; i < 3; i++) {
            const int idx = tid + i * 256;
            const int row = idx >> 3, c4 = idx & 7;
            *(uint4*)(As + SWZB(row * 128 + c4 * 16)) = ar[i];
        }
        #pragma unroll
        for (int i = 0; i < 2; i++) {
            const int task = tid + i * 256;
            const int tp = task & 31, chg = task >> 5;
            const ushort* ha = (const ushort*)&bra[i];
            const ushort* hb = (const ushort*)&brb[i];
            #pragma unroll
            for (int j = 0; j < 8; j++) {
                const uint32_t pv = (uint32_t)ha[j] | ((uint32_t)hb[j] << 16);
                *(uint32_t*)(Bs + SWZB((chg * 8 + j) * 128 + tp * 4)) = pv;
            }
        }
    };

    gload(0);
    #pragma unroll 1
    for (int c = 0; c < 3; c++) {
        sstore();
        if (c < 2) gload(c + 1);
        __syncthreads();
        #pragma unroll
        for (int ks = 0; ks < 4; ks++) {
            const int kb = ks * 32;
            uint32_t afr[3][4];
            #pragma unroll
            for (int fm = 0; fm < 3; fm++)
                ld_afrag(afr[fm], Asu, wm * 48 + fm * 16, kb, lane);
            uint32_t bfr[2][4];
            #pragma unroll
            for (int fp = 0; fp < 2; fp++)
                ld_bfrag2(bfr[fp], Bsu, wn * 32 + fp * 16, kb, lane);
            #pragma unroll
            for (int fm = 0; fm < 3; fm++)
                #pragma unroll
                for (int fp = 0; fp < 2; fp++) {
                    mma_f16(acc[fm][fp * 2 + 0], afr[fm], &bfr[fp][0]);
                    mma_f16(acc[fm][fp * 2 + 1], afr[fm], &bfr[fp][2]);
                }
        }
        __syncthreads();
    }

    #pragma unroll
    for (int fm = 0; fm < 3; fm++) {
        #pragma unroll
        for (int h = 0; h < 2; h++) {
            const int m = m0 + wm * 48 + fm * 16 + lr + h * 8;
            if (m < NN) {
                #pragma unroll
                for (int fn = 0; fn < 4; fn++) {
                    const int n = bc + wn * 32 + fn * 8 + lc * 2;
                    *(half2*)(g_Zh + ((size_t)b * NN + m) * CC + n) =
                        __floats2half2_rn(acc[fm][fn][h * 2 + 0], acc[fm][fn][h * 2 + 1]);
                }
            }
        }
    }
}

// ---------------- conversion / pack kernels ----------------
__global__ void cvt_x(const float* __restrict__ x) {
    const size_t i = ((size_t)blockIdx.x * 256 + threadIdx.x) * 8;
    const float4 v0 = *(const float4*)(x + i);
    const float4 v1 = *(const float4*)(x + i + 4);
    __half2 o[4];
    o[0] = __floats2half2_rn(v0.x, v0.y);
    o[1] = __floats2half2_rn(v0.z, v0.w);
    o[2] = __floats2half2_rn(v1.x, v1.y);
    o[3] = __floats2half2_rn(v1.z, v1.w);
    *(uint4*)(g_xh + i) = *(const uint4*)o;
}

__global__ void pack_wqk(const float* __restrict__ Wq, const float* __restrict__ Wk) {
    __shared__ float t[32][33];
    int k0 = blockIdx.x * 32, n0 = blockIdx.y * 32, z = blockIdx.z;
    const float* W = z ? Wk : Wq;
    int tx = threadIdx.x, ty = threadIdx.y;
    t[ty][tx] = W[(size_t)(k0 + ty) * RR + n0 + tx];
    __syncthreads();
    g_Wqkth[(size_t)(z * RR + n0 + ty) * CC + k0 + tx] = __float2half_rn(t[tx][ty]);
}

__global__ void pack_wg(const float* __restrict__ Wg) {
    __shared__ float t[32][33];
    int k0 = blockIdx.x * 32, n0 = blockIdx.y * 32;
    int tx = threadIdx.x, ty = threadIdx.y;
    t[ty][tx] = Wg[(size_t)(k0 + ty) * CC + n0 + tx];
    __syncthreads();
    g_Wgth[(size_t)(n0 + ty) * CC + k0 + tx] = __float2half_rn(t[tx][ty]);
}

// ---------------- softmax + combine: warp-per-row, f32 scores -> fp16 A_comb ----------------
__global__ void __launch_bounds__(256) softmax_combine(const float* __restrict__ alpha,
                                                       const float* __restrict__ A_phys) {
    const int wid = threadIdx.x >> 5, lane = threadIdx.x & 31;
    const int row = blockIdx.x * 8 + wid;   // global row in [0, MM)
    const int b = row / NN, n = row - b * NN;
    const float* Srow = g_S + (size_t)(b * NN + n) * NN;
    __half* Drow = g_Sh + (size_t)(b * NN + n) * 192;

    float v[6];
    #pragma unroll
    for (int j = 0; j < 6; j++) {
        const int t = lane + j * 32;
        v[j] = (t < NN) ? Srow[t] : -3.0e38f;
    }
    float mx = v[0];
    #pragma unroll
    for (int j = 1; j < 6; j++) mx = fmaxf(mx, v[j]);
    #pragma unroll
    for (int o = 16; o > 0; o >>= 1) mx = fmaxf(mx, __shfl_xor_sync(0xffffffff, mx, o));

    float e[6], s = 0.f;
    #pragma unroll
    for (int j = 0; j < 6; j++) {
        const int t = lane + j * 32;
        e[j] = (t < NN) ? expf(v[j] - mx) : 0.f;
        s += e[j];
    }
    #pragma unroll
    for (int o = 16; o > 0; o >>= 1) s += __shfl_xor_sync(0xffffffff, s, o);

    const float a = 1.f / (1.f + expf(-alpha[0]));
    const float inv = (1.f - a) / s;
    #pragma unroll
    for (int j = 0; j < 6; j++) {
        const int t = lane + j * 32;
        float outv = 0.f;
        if (t < NN) outv = a * A_phys[n * NN + t] + e[j] * inv;
        Drow[t] = __float2half_rn(outv);
    }
}

// ---------------- LayerNorm: warp-per-row (fp16 in, fp32 out) ----------------
__global__ void __launch_bounds__(256) ln_kernel(const float* __restrict__ gamma,
                                                 const float* __restrict__ beta,
                                                 float* __restrict__ out) {
    const int wid = threadIdx.x >> 5, lane = threadIdx.x & 31;
    const size_t row = (size_t)blockIdx.x * 8 + wid;
    const __half* hp = g_Hh + row * CC;

    uint4 raw[3];
    float v[3][8];
    float s = 0.f, sq = 0.f;
    #pragma unroll
    for (int i = 0; i < 3; i++) {
        raw[i] = *(const uint4*)(hp + (i * 32 + lane) * 8);
        const uint32_t* w = (const uint32_t*)&raw[i];
        #pragma unroll
        for (int p = 0; p < 4; p++) {
            const float2 f = __half22float2(*(const half2*)&w[p]);
            v[i][p * 2 + 0] = f.x;
            v[i][p * 2 + 1] = f.y;
            s  += f.x + f.y;
            sq += f.x * f.x + f.y * f.y;
        }
    }
    #pragma unroll
    for (int o = 16; o > 0; o >>= 1) {
        s  += __shfl_xor_sync(0xffffffff, s, o);
        sq += __shfl_xor_sync(0xffffffff, sq, o);
    }
    const float mu  = s * (1.f / 768.f);
    const float var = sq * (1.f / 768.f) - mu * mu;
    const float inv = rsqrtf(var + 1e-5f);

    float* op = out + row * CC;
    #pragma unroll
    for (int i = 0; i < 3; i++) {
        const int e0 = (i * 32 + lane) * 8;
        #pragma unroll
        for (int q = 0; q < 2; q++) {
            const float4 g  = *(const float4*)(gamma + e0 + q * 4);
            const float4 be = *(const float4*)(beta  + e0 + q * 4);
            float4 o4;
            o4.x = (v[i][q * 4 + 0] - mu) * inv * g.x + be.x;
            o4.y = (v[i][q * 4 + 1] - mu) * inv * g.y + be.y;
            o4.z = (v[i][q * 4 + 2] - mu) * inv * g.z + be.z;
            o4.w = (v[i][q * 4 + 3] - mu) * inv * g.w + be.w;
            *(float4*)(op + e0 + q * 4) = o4;
        }
    }
}

// ---------------- host launcher ----------------
#define GEMM_SMEM 65536

extern "C" void kernel_launch(void* const* d_in, const int* in_sizes, int n_in,
                              void* d_out, int out_size) {
    const float* x     = (const float*)d_in[0];
    const float* Wq    = (const float*)d_in[1];
    const float* bq    = (const float*)d_in[2];
    const float* Wk    = (const float*)d_in[3];
    const float* bk    = (const float*)d_in[4];
    const float* Wg    = (const float*)d_in[5];
    const float* bg    = (const float*)d_in[6];
    const float* gamma = (const float*)d_in[7];
    const float* beta  = (const float*)d_in[8];
    const float* alpha = (const float*)d_in[9];
    const float* A_phys= (const float*)d_in[10];
    float* out = (float*)d_out;

    cudaFuncSetAttribute(gemm_h<384, false, true>, cudaFuncAttributeMaxDynamicSharedMemorySize, GEMM_SMEM);
    cudaFuncSetAttribute(gemm_h<768, true, false>, cudaFuncAttributeMaxDynamicSharedMemorySize, GEMM_SMEM);

    void *xh, *wqkt, *wgt, *qk, *zh, *hh;
    cudaGetSymbolAddress(&xh,   g_xh);
    cudaGetSymbolAddress(&wqkt, g_Wqkth);
    cudaGetSymbolAddress(&wgt,  g_Wgth);
    cudaGetSymbolAddress(&qk,   g_QKh);
    cudaGetSymbolAddress(&zh,   g_Zh);
    cudaGetSymbolAddress(&hh,   g_Hh);

    dim3 b32(32, 32);
    cvt_x<<<17280, 256>>>(x);
    pack_wqk<<<dim3(24, 6, 2), b32>>>(Wq, Wk);
    pack_wg<<<dim3(24, 24), b32>>>(Wg);

    gemm_h<384, false, true><<<dim3(3, 360), 256, GEMM_SMEM>>>(
        (const __half*)xh, (const __half*)wqkt, bq, bk, nullptr, (__half*)qk);
    scores_h<<<dim3(2, 256), 256>>>();
    softmax_combine<<<MM / 8, 256>>>(alpha, A_phys);
    aggregate_h<<<dim3(6, 2, 256), 256>>>();
    gemm_h<768, true, false><<<dim3(6, 360), 256, GEMM_SMEM>>>(
        (const __half*)zh, (const __half*)wgt, bg, nullptr,
        (const __half*)xh, (__half*)hh);
    ln_kernel<<<MM / 8, 256>>>(gamma, beta, out);
}

// round 15
// speedup vs baseline: 1.0002x; 1.0002x over previous
#include <cuda_runtime.h>
#include <cuda_fp16.h>
#include <math.h>
#include <stdint.h>

#define BB 256
#define NN 180
#define CC 768
#define RR 192
#define MM (BB*NN)     // 46080
#define NCHUNK (CC/64) // 12 K-chunks of 64 halfs (128B)

// ---------------- scratch (static device allocations) ----------------
__device__ __half g_xh[(size_t)MM * CC];       // fp16 copy of x
__device__ __half g_Wqkth[384 * 768];          // [n][k] fp16 Wq^T | Wk^T
__device__ __half g_Wgth[768 * 768];           // [n][k] fp16 Wg^T
__device__ __half g_QKh[(size_t)MM * 384];     // [M, 384] Q|K fp16
__device__ float  g_S[(size_t)BB * NN * NN];   // raw scores f32
__device__ __half g_Sh[(size_t)BB * NN * 192]; // A_comb fp16, rows padded to 192
__device__ __half g_Zh[(size_t)MM * CC];       // A_comb @ x, fp16
__device__ __half g_Hh[(size_t)MM * CC];       // pre-LN h, fp16

// ---------------- helpers ----------------
__device__ __forceinline__ uint32_t smem_u32(const void* p) {
    uint32_t a;
    asm("{ .reg .u64 t; cvta.to.shared.u64 t, %1; cvt.u32.u64 %0, t; }" : "=r"(a) : "l"(p));
    return a;
}
// 128-byte swizzle on byte offsets (rows are 128B)
#define SWZB(o) ((o) ^ (((o) >> 3) & 0x70))

__device__ __forceinline__ void cp16(uint32_t dst, const void* src) {
    asm volatile("cp.async.ca.shared.global [%0], [%1], 16;"
                 :: "r"(dst), "l"(src) : "memory");
}
#define CP_COMMIT() asm volatile("cp.async.commit_group;" ::: "memory")
#define CP_WAIT1()  asm volatile("cp.async.wait_group 1;" ::: "memory")
#define CP_WAIT0()  asm volatile("cp.async.wait_group 0;" ::: "memory")

__device__ __forceinline__ void ldsm_x4(uint32_t* r, uint32_t addr) {
    asm volatile("ldmatrix.sync.aligned.m8n8.x4.shared.b16 {%0,%1,%2,%3}, [%4];"
                 : "=r"(r[0]), "=r"(r[1]), "=r"(r[2]), "=r"(r[3]) : "r"(addr));
}

__device__ __forceinline__ void mma_f16(float* c, const uint32_t* a, const uint32_t* b) {
    asm volatile(
        "mma.sync.aligned.m16n8k16.row.col.f32.f16.f16.f32 "
        "{%0,%1,%2,%3}, {%4,%5,%6,%7}, {%8,%9}, {%0,%1,%2,%3};"
        : "+f"(c[0]), "+f"(c[1]), "+f"(c[2]), "+f"(c[3])
        : "r"(a[0]), "r"(a[1]), "r"(a[2]), "r"(a[3]), "r"(b[0]), "r"(b[1]));
}

// A fragment via ldmatrix.x4: rows base_r..base_r+15, k bytes kb..kb+31
__device__ __forceinline__ void ld_afrag(uint32_t* afr, uint32_t Asu,
                                         int base_r, int kb, int lane) {
    const int row = base_r + (lane & 15);
    ldsm_x4(afr, Asu + SWZB(row * 128 + kb + ((lane >> 4) << 4)));
}
// B fragment pair via ldmatrix.x4: n rows base_n..+15 (two n8 blocks), k bytes kb..kb+31
__device__ __forceinline__ void ld_bfrag2(uint32_t* b4, uint32_t Bsu,
                                          int base_n, int kb, int lane) {
    const int n = base_n + ((lane >> 4) << 3) + (lane & 7);
    const int koff = kb + (((lane >> 3) & 1) << 4);
    ldsm_x4(b4, Bsu + SWZB(n * 128 + koff));
}

// ================== main GEMM: Out[M,NC] = A[M,768]h @ Wt[NC,768]h^T ==================
// Tile 128x128xK64, 256 threads (8 warps = 4m x 2n), 2-stage cp.async, 1 sync/chunk.
template<int NC, bool RELU, bool SPLITB>
__global__ void __launch_bounds__(256, 2) gemm_h(
    const __half* __restrict__ A,
    const __half* __restrict__ Wt,
    const float* __restrict__ bias0,
    const float* __restrict__ bias1,
    const __half* __restrict__ residh,
    __half* __restrict__ OutH)
{
    extern __shared__ char smc[];     // 2 stages x (A 16KB + B 16KB)
    const uint32_t sbase = smem_u32(smc);
    const int tid  = threadIdx.x;
    const int lane = tid & 31;
    const int wid  = tid >> 5;
    const int wm   = wid & 3;
    const int wn   = wid >> 2;
    const int lr   = lane >> 2;
    const int lc   = lane & 3;
    const int bm   = blockIdx.y * 128;
    const int bn   = blockIdx.x * 128;

    float acc[2][8][4];
    #pragma unroll
    for (int i = 0; i < 2; i++)
        #pragma unroll
        for (int j = 0; j < 8; j++)
            #pragma unroll
            for (int k = 0; k < 4; k++) acc[i][j][k] = 0.f;

    const int lrow = tid >> 3;
    const int lc4  = tid & 7;

    auto issue_load = [&](int c, int s) {
        const uint32_t abase = sbase + (uint32_t)s * 32768u;
        const uint32_t bbase = abase + 16384u;
        const int k0 = c * 64;
        #pragma unroll
        for (int i = 0; i < 4; i++) {
            const int row = lrow + i * 32;
            const uint32_t soff = SWZB(row * 128 + lc4 * 16);
            cp16(abase + soff, A  + (size_t)(bm + row) * CC + k0 + lc4 * 8);
            cp16(bbase + soff, Wt + (size_t)(bn + row) * CC + k0 + lc4 * 8);
        }
        CP_COMMIT();
    };

    issue_load(0, 0);

    #pragma unroll 1
    for (int c = 0; c < NCHUNK; c++) {
        CP_WAIT0();
        __syncthreads();
        if (c + 1 < NCHUNK) issue_load(c + 1, (c + 1) & 1);

        const uint32_t Asu = sbase + (uint32_t)(c & 1) * 32768u;
        const uint32_t Bsu = Asu + 16384u;

        #pragma unroll
        for (int ks = 0; ks < 4; ks++) {
            const int kb = ks * 32;
            uint32_t afr[2][4];
            #pragma unroll
            for (int fm = 0; fm < 2; fm++)
                ld_afrag(afr[fm], Asu, wm * 32 + fm * 16, kb, lane);
            uint32_t bfr[4][4];
            #pragma unroll
            for (int fp = 0; fp < 4; fp++)
                ld_bfrag2(bfr[fp], Bsu, wn * 64 + fp * 16, kb, lane);
            #pragma unroll
            for (int fm = 0; fm < 2; fm++)
                #pragma unroll
                for (int fp = 0; fp < 4; fp++) {
                    mma_f16(acc[fm][fp * 2 + 0], afr[fm], &bfr[fp][0]);
                    mma_f16(acc[fm][fp * 2 + 1], afr[fm], &bfr[fp][2]);
                }
        }
    }

    // ---- epilogue ----
    #pragma unroll
    for (int fm = 0; fm < 2; fm++) {
        #pragma unroll
        for (int h = 0; h < 2; h++) {
            const int m = bm + wm * 32 + fm * 16 + lr + h * 8;
            #pragma unroll
            for (int fn = 0; fn < 8; fn++) {
                const int n = bn + wn * 64 + fn * 8 + lc * 2;
                float b0, b1;
                if (SPLITB) {
                    b0 = (n < RR) ? bias0[n] : bias1[n - RR];
                    b1 = (n + 1 < RR) ? bias0[n + 1] : bias1[n + 1 - RR];
                } else {
                    b0 = bias0[n]; b1 = bias0[n + 1];
                }
                float vx = acc[fm][fn][h * 2 + 0] + b0;
                float vy = acc[fm][fn][h * 2 + 1] + b1;
                if (RELU) {
                    const float2 rx = __half22float2(
                        *(const half2*)(residh + (size_t)m * NC + n));
                    vx = fmaxf(vx, 0.f) + rx.x;
                    vy = fmaxf(vy, 0.f) + rx.y;
                }
                *(half2*)(OutH + (size_t)m * NC + n) = __floats2half2_rn(vx, vy);
            }
        }
    }
}

// ================== scores = Q @ K^T / sqrt(R) (fp16 tensor, batched) ==================
// Per batch: M=192 (180 valid), N=96, K=192 (3 chunks of 64). grid (2, 256).
__global__ void __launch_bounds__(256, 1) scores_h() {
    __shared__ __align__(128) char As[192 * 128];   // Q tile [192][64h]
    __shared__ __align__(128) char Bs[96 * 128];    // K tile [96][64h]
    const int tid = threadIdx.x;
    const int wid = tid >> 5, lane = tid & 31;
    const int wm = wid & 3, wn = wid >> 2;
    const int lr = lane >> 2, lc = lane & 3;
    const int b  = blockIdx.y;
    const int bn = blockIdx.x * 96;
    const __half* qb = g_QKh + (size_t)b * NN * 384;
    const uint32_t Asu = smem_u32(As), Bsu = smem_u32(Bs);

    float acc[3][6][4];
    #pragma unroll
    for (int i = 0; i < 3; i++)
        #pragma unroll
        for (int j = 0; j < 6; j++)
            #pragma unroll
            for (int k = 0; k < 4; k++) acc[i][j][k] = 0.f;

    uint4 ar[6], br[3];
    auto gload = [&](int c) {
        const int k0 = c * 64;
        #pragma unroll
        for (int i = 0; i < 6; i++) {
            const int idx = tid + i * 256;
            const int row = idx >> 3, c4 = idx & 7;
            uint4 v = make_uint4(0, 0, 0, 0);
            if (row < NN) v = *(const uint4*)(qb + (size_t)row * 384 + k0 + c4 * 8);
            ar[i] = v;
        }
        #pragma unroll
        for (int i = 0; i < 3; i++) {
            const int idx = tid + i * 256;
            const int row = idx >> 3, c4 = idx & 7;
            uint4 v = make_uint4(0, 0, 0, 0);
            if (bn + row < NN) v = *(const uint4*)(qb + (size_t)(bn + row) * 384 + 192 + k0 + c4 * 8);
            br[i] = v;
        }
    };
    auto sstore = [&]() {
        #pragma unroll
        for (int i = 0; i < 6; i++) {
            const int idx = tid + i * 256;
            const int row = idx >> 3, c4 = idx & 7;
            *(uint4*)(As + SWZB(row * 128 + c4 * 16)) = ar[i];
        }
        #pragma unroll
        for (int i = 0; i < 3; i++) {
            const int idx = tid + i * 256;
            const int row = idx >> 3, c4 = idx & 7;
            *(uint4*)(Bs + SWZB(row * 128 + c4 * 16)) = br[i];
        }
    };

    gload(0);
    #pragma unroll 1
    for (int c = 0; c < 3; c++) {
        sstore();
        if (c < 2) gload(c + 1);
        __syncthreads();
        #pragma unroll
        for (int ks = 0; ks < 4; ks++) {
            const int kb = ks * 32;
            uint32_t afr[3][4];
            #pragma unroll
            for (int fm = 0; fm < 3; fm++)
                ld_afrag(afr[fm], Asu, wm * 48 + fm * 16, kb, lane);
            uint32_t bfr[3][4];
            #pragma unroll
            for (int fp = 0; fp < 3; fp++)
                ld_bfrag2(bfr[fp], Bsu, wn * 48 + fp * 16, kb, lane);
            #pragma unroll
            for (int fm = 0; fm < 3; fm++)
                #pragma unroll
                for (int fp = 0; fp < 3; fp++) {
                    mma_f16(acc[fm][fp * 2 + 0], afr[fm], &bfr[fp][0]);
                    mma_f16(acc[fm][fp * 2 + 1], afr[fm], &bfr[fp][2]);
                }
        }
        __syncthreads();
    }

    const float scale = 0.07216878364870323f;   // 1/sqrt(192)
    float* Sb = g_S + (size_t)b * NN * NN;
    #pragma unroll
    for (int fm = 0; fm < 3; fm++) {
        #pragma unroll
        for (int h = 0; h < 2; h++) {
            const int m = wm * 48 + fm * 16 + lr + h * 8;
            if (m < NN) {
                #pragma unroll
                for (int fn = 0; fn < 6; fn++) {
                    const int n = bn + wn * 48 + fn * 8 + lc * 2;
                    if (n < NN)     Sb[(size_t)m * NN + n]     = acc[fm][fn][h * 2 + 0] * scale;
                    if (n + 1 < NN) Sb[(size_t)m * NN + n + 1] = acc[fm][fn][h * 2 + 1] * scale;
                }
            }
        }
    }
}

// ================== z = A_comb @ x (fp16 tensor, batched) ==================
// Split-M: per block M=96 (half of 192-pad), N=128 channels, K=192 tokens.
// grid (6, 2, 256). 8 warps = 2m x 4n (warp tile 48x32), acc 48 floats -> 2 CTAs/SM.
__global__ void __launch_bounds__(256, 2) aggregate_h() {
    __shared__ __align__(128) char As[96 * 128];    // A_comb half-tile [96 rows][64 tok]
    __shared__ __align__(128) char Bs[128 * 128];   // x^T [128 ch][64 tok]
    const int tid = threadIdx.x;
    const int wid = tid >> 5, lane = tid & 31;
    const int wm = wid & 1, wn = wid >> 1;
    const int lr = lane >> 2, lc = lane & 3;
    const int bc = blockIdx.x * 128;
    const int m0 = blockIdx.y * 96;
    const int b  = blockIdx.z;
    const __half* Sb = g_Sh + (size_t)b * NN * 192;
    const __half* xb = g_xh + (size_t)b * NN * CC;
    const uint32_t Asu = smem_u32(As), Bsu = smem_u32(Bs);

    float acc[3][4][4];
    #pragma unroll
    for (int i = 0; i < 3; i++)
        #pragma unroll
        for (int j = 0; j < 4; j++)
            #pragma unroll
            for (int k = 0; k < 4; k++) acc[i][j][k] = 0.f;

    uint4 ar[3], bra[2], brb[2];
    auto gload = [&](int c) {
        const int k0 = c * 64;
        #pragma unroll
        for (int i = 0; i < 3; i++) {            // A: 96 rows x 8 units
            const int idx = tid + i * 256;
            const int row = idx >> 3, c4 = idx & 7;
            uint4 v = make_uint4(0, 0, 0, 0);
            if (m0 + row < NN) v = *(const uint4*)(Sb + (size_t)(m0 + row) * 192 + k0 + c4 * 8);
            ar[i] = v;
        }
        #pragma unroll
        for (int i = 0; i < 2; i++) {
            const int task = tid + i * 256;
            const int tp = task & 31, chg = task >> 5;
            const int tokA = k0 + 2 * tp, tokB = tokA + 1;
            uint4 va = make_uint4(0, 0, 0, 0), vb = make_uint4(0, 0, 0, 0);
            if (tokA < NN) va = *(const uint4*)(xb + (size_t)tokA * CC + bc + chg * 8);
            if (tokB < NN) vb = *(const uint4*)(xb + (size_t)tokB * CC + bc + chg * 8);
            bra[i] = va; brb[i] = vb;
        }
    };
    auto sstore = [&]() {
        #pragma unroll
        for (int i = 0; i < 3; i++) {
            const int idx = tid + i * 256;
            const int row = idx >> 3, c4 = idx & 7;
            *(uint4*)(As + SWZB(row * 128 + c4 * 16)) = ar[i];
        }
        #pragma unroll
        for (int i = 0; i < 2; i++) {
            const int task = tid + i * 256;
            const int tp = task & 31, chg = task >> 5;
            const ushort* ha = (const ushort*)&bra[i];
            const ushort* hb = (const ushort*)&brb[i];
            #pragma unroll
            for (int j = 0; j < 8; j++) {
                const uint32_t pv = (uint32_t)ha[j] | ((uint32_t)hb[j] << 16);
                *(uint32_t*)(Bs + SWZB((chg * 8 + j) * 128 + tp * 4)) = pv;
            }
        }
    };

    gload(0);
    #pragma unroll 1
    for (int c = 0; c < 3; c++) {
        sstore();
        if (c < 2) gload(c + 1);
        __syncthreads();
        #pragma unroll
        for (int ks = 0; ks < 4; ks++) {
            const int kb = ks * 32;
            uint32_t afr[3][4];
            #pragma unroll
            for (int fm = 0; fm < 3; fm++)
                ld_afrag(afr[fm], Asu, wm * 48 + fm * 16, kb, lane);
            uint32_t bfr[2][4];
            #pragma unroll
            for (int fp = 0; fp < 2; fp++)
                ld_bfrag2(bfr[fp], Bsu, wn * 32 + fp * 16, kb, lane);
            #pragma unroll
            for (int fm = 0; fm < 3; fm++)
                #pragma unroll
                for (int fp = 0; fp < 2; fp++) {
                    mma_f16(acc[fm][fp * 2 + 0], afr[fm], &bfr[fp][0]);
                    mma_f16(acc[fm][fp * 2 + 1], afr[fm], &bfr[fp][2]);
                }
        }
        __syncthreads();
    }

    #pragma unroll
    for (int fm = 0; fm < 3; fm++) {
        #pragma unroll
        for (int h = 0; h < 2; h++) {
            const int m = m0 + wm * 48 + fm * 16 + lr + h * 8;
            if (m < NN) {
                #pragma unroll
                for (int fn = 0; fn < 4; fn++) {
                    const int n = bc + wn * 32 + fn * 8 + lc * 2;
                    *(half2*)(g_Zh + ((size_t)b * NN + m) * CC + n) =
                        __floats2half2_rn(acc[fm][fn][h * 2 + 0], acc[fm][fn][h * 2 + 1]);
                }
            }
        }
    }
}

// ---------------- conversion / pack kernels ----------------
__global__ void cvt_x(const float* __restrict__ x) {
    const size_t i = ((size_t)blockIdx.x * 256 + threadIdx.x) * 8;
    const float4 v0 = *(const float4*)(x + i);
    const float4 v1 = *(const float4*)(x + i + 4);
    __half2 o[4];
    o[0] = __floats2half2_rn(v0.x, v0.y);
    o[1] = __floats2half2_rn(v0.z, v0.w);
    o[2] = __floats2half2_rn(v1.x, v1.y);
    o[3] = __floats2half2_rn(v1.z, v1.w);
    *(uint4*)(g_xh + i) = *(const uint4*)o;
}

__global__ void pack_wqk(const float* __restrict__ Wq, const float* __restrict__ Wk) {
    __shared__ float t[32][33];
    int k0 = blockIdx.x * 32, n0 = blockIdx.y * 32, z = blockIdx.z;
    const float* W = z ? Wk : Wq;
    int tx = threadIdx.x, ty = threadIdx.y;
    t[ty][tx] = W[(size_t)(k0 + ty) * RR + n0 + tx];
    __syncthreads();
    g_Wqkth[(size_t)(z * RR + n0 + ty) * CC + k0 + tx] = __float2half_rn(t[tx][ty]);
}

__global__ void pack_wg(const float* __restrict__ Wg) {
    __shared__ float t[32][33];
    int k0 = blockIdx.x * 32, n0 = blockIdx.y * 32;
    int tx = threadIdx.x, ty = threadIdx.y;
    t[ty][tx] = Wg[(size_t)(k0 + ty) * CC + n0 + tx];
    __syncthreads();
    g_Wgth[(size_t)(n0 + ty) * CC + k0 + tx] = __float2half_rn(t[tx][ty]);
}

// ---------------- softmax + combine: warp-per-row, f32 scores -> fp16 A_comb ----------------
__global__ void __launch_bounds__(256) softmax_combine(const float* __restrict__ alpha,
                                                       const float* __restrict__ A_phys) {
    const int wid = threadIdx.x >> 5, lane = threadIdx.x & 31;
    const int row = blockIdx.x * 8 + wid;   // global row in [0, MM)
    const int b = row / NN, n = row - b * NN;
    const float* Srow = g_S + (size_t)(b * NN + n) * NN;
    __half* Drow = g_Sh + (size_t)(b * NN + n) * 192;

    float v[6];
    #pragma unroll
    for (int j = 0; j < 6; j++) {
        const int t = lane + j * 32;
        v[j] = (t < NN) ? Srow[t] : -3.0e38f;
    }
    float mx = v[0];
    #pragma unroll
    for (int j = 1; j < 6; j++) mx = fmaxf(mx, v[j]);
    #pragma unroll
    for (int o = 16; o > 0; o >>= 1) mx = fmaxf(mx, __shfl_xor_sync(0xffffffff, mx, o));

    float e[6], s = 0.f;
    #pragma unroll
    for (int j = 0; j < 6; j++) {
        const int t = lane + j * 32;
        e[j] = (t < NN) ? expf(v[j] - mx) : 0.f;
        s += e[j];
    }
    #pragma unroll
    for (int o = 16; o > 0; o >>= 1) s += __shfl_xor_sync(0xffffffff, s, o);

    const float a = 1.f / (1.f + expf(-alpha[0]));
    const float inv = (1.f - a) / s;
    #pragma unroll
    for (int j = 0; j < 6; j++) {
        const int t = lane + j * 32;
        float outv = 0.f;
        if (t < NN) outv = a * A_phys[n * NN + t] + e[j] * inv;
        Drow[t] = __float2half_rn(outv);
    }
}

// ---------------- LayerNorm: warp-per-row (fp16 in, fp32 out) ----------------
__global__ void __launch_bounds__(256) ln_kernel(const float* __restrict__ gamma,
                                                 const float* __restrict__ beta,
                                                 float* __restrict__ out) {
    const int wid = threadIdx.x >> 5, lane = threadIdx.x & 31;
    const size_t row = (size_t)blockIdx.x * 8 + wid;
    const __half* hp = g_Hh + row * CC;

    uint4 raw[3];
    float v[3][8];
    float s = 0.f, sq = 0.f;
    #pragma unroll
    for (int i = 0; i < 3; i++) {
        raw[i] = *(const uint4*)(hp + (i * 32 + lane) * 8);
        const uint32_t* w = (const uint32_t*)&raw[i];
        #pragma unroll
        for (int p = 0; p < 4; p++) {
            const float2 f = __half22float2(*(const half2*)&w[p]);
            v[i][p * 2 + 0] = f.x;
            v[i][p * 2 + 1] = f.y;
            s  += f.x + f.y;
            sq += f.x * f.x + f.y * f.y;
        }
    }
    #pragma unroll
    for (int o = 16; o > 0; o >>= 1) {
        s  += __shfl_xor_sync(0xffffffff, s, o);
        sq += __shfl_xor_sync(0xffffffff, sq, o);
    }
    const float mu  = s * (1.f / 768.f);
    const float var = sq * (1.f / 768.f) - mu * mu;
    const float inv = rsqrtf(var + 1e-5f);

    float* op = out + row * CC;
    #pragma unroll
    for (int i = 0; i < 3; i++) {
        const int e0 = (i * 32 + lane) * 8;
        #pragma unroll
        for (int q = 0; q < 2; q++) {
            const float4 g  = *(const float4*)(gamma + e0 + q * 4);
            const float4 be = *(const float4*)(beta  + e0 + q * 4);
            float4 o4;
            o4.x = (v[i][q * 4 + 0] - mu) * inv * g.x + be.x;
            o4.y = (v[i][q * 4 + 1] - mu) * inv * g.y + be.y;
            o4.z = (v[i][q * 4 + 2] - mu) * inv * g.z + be.z;
            o4.w = (v[i][q * 4 + 3] - mu) * inv * g.w + be.w;
            *(float4*)(op + e0 + q * 4) = o4;
        }
    }
}

// ---------------- host launcher ----------------
#define GEMM_SMEM 65536

extern "C" void kernel_launch(void* const* d_in, const int* in_sizes, int n_in,
                              void* d_out, int out_size) {
    const float* x     = (const float*)d_in[0];
    const float* Wq    = (const float*)d_in[1];
    const float* bq    = (const float*)d_in[2];
    const float* Wk    = (const float*)d_in[3];
    const float* bk    = (const float*)d_in[4];
    const float* Wg    = (const float*)d_in[5];
    const float* bg    = (const float*)d_in[6];
    const float* gamma = (const float*)d_in[7];
    const float* beta  = (const float*)d_in[8];
    const float* alpha = (const float*)d_in[9];
    const float* A_phys= (const float*)d_in[10];
    float* out = (float*)d_out;

    cudaFuncSetAttribute(gemm_h<384, false, true>, cudaFuncAttributeMaxDynamicSharedMemorySize, GEMM_SMEM);
    cudaFuncSetAttribute(gemm_h<768, true, false>, cudaFuncAttributeMaxDynamicSharedMemorySize, GEMM_SMEM);

    void *xh, *wqkt, *wgt, *qk, *zh, *hh;
    cudaGetSymbolAddress(&xh,   g_xh);
    cudaGetSymbolAddress(&wqkt, g_Wqkth);
    cudaGetSymbolAddress(&wgt,  g_Wgth);
    cudaGetSymbolAddress(&qk,   g_QKh);
    cudaGetSymbolAddress(&zh,   g_Zh);
    cudaGetSymbolAddress(&hh,   g_Hh);

    dim3 b32(32, 32);
    cvt_x<<<17280, 256>>>(x);
    pack_wqk<<<dim3(24, 6, 2), b32>>>(Wq, Wk);
    pack_wg<<<dim3(24, 24), b32>>>(Wg);

    gemm_h<384, false, true><<<dim3(3, 360), 256, GEMM_SMEM>>>(
        (const __half*)xh, (const __half*)wqkt, bq, bk, nullptr, (__half*)qk);
    scores_h<<<dim3(2, 256), 256>>>();
    softmax_combine<<<MM / 8, 256>>>(alpha, A_phys);
    aggregate_h<<<dim3(6, 2, 256), 256>>>();
    gemm_h<768, true, false><<<dim3(6, 360), 256, GEMM_SMEM>>>(
        (const __half*)zh, (const __half*)wgt, bg, nullptr,
        (const __half*)xh, (__half*)hh);
    ln_kernel<<<MM / 8, 256>>>(gamma, beta, out);
}

// round 16
// speedup vs baseline: 1.0276x; 1.0274x over previous
#include <cuda_runtime.h>
#include <cuda_fp16.h>
#include <math.h>
#include <stdint.h>

#define BB 256
#define NN 180
#define CC 768
#define RR 192
#define MM (BB*NN)     // 46080
#define NCHUNK (CC/64) // 12 K-chunks of 64 halfs (128B)

// ---------------- scratch (static device allocations) ----------------
__device__ __half g_xh[(size_t)MM * CC];       // fp16 copy of x
__device__ __half g_Wqkth[384 * 768];          // [n][k] fp16 Wq^T | Wk^T
__device__ __half g_Wgth[768 * 768];           // [n][k] fp16 Wg^T
__device__ __half g_QKh[(size_t)MM * 384];     // [M, 384] Q|K fp16
__device__ float  g_S[(size_t)BB * NN * NN];   // raw scores f32
__device__ __half g_Sh[(size_t)BB * NN * 192]; // A_comb fp16, rows padded to 192
__device__ __half g_Zh[(size_t)MM * CC];       // A_comb @ x, fp16
__device__ __half g_Hh[(size_t)MM * CC];       // pre-LN h, fp16

// ---------------- helpers ----------------
__device__ __forceinline__ uint32_t smem_u32(const void* p) {
    uint32_t a;
    asm("{ .reg .u64 t; cvta.to.shared.u64 t, %1; cvt.u32.u64 %0, t; }" : "=r"(a) : "l"(p));
    return a;
}
// 128-byte swizzle on byte offsets (rows are 128B)
#define SWZB(o) ((o) ^ (((o) >> 3) & 0x70))

__device__ __forceinline__ void cp16(uint32_t dst, const void* src) {
    asm volatile("cp.async.ca.shared.global [%0], [%1], 16;"
                 :: "r"(dst), "l"(src) : "memory");
}
#define CP_COMMIT() asm volatile("cp.async.commit_group;" ::: "memory")
#define CP_WAIT1()  asm volatile("cp.async.wait_group 1;" ::: "memory")
#define CP_WAIT0()  asm volatile("cp.async.wait_group 0;" ::: "memory")

__device__ __forceinline__ void ldsm_x4(uint32_t* r, uint32_t addr) {
    asm volatile("ldmatrix.sync.aligned.m8n8.x4.shared.b16 {%0,%1,%2,%3}, [%4];"
                 : "=r"(r[0]), "=r"(r[1]), "=r"(r[2]), "=r"(r[3]) : "r"(addr));
}

__device__ __forceinline__ void mma_f16(float* c, const uint32_t* a, const uint32_t* b) {
    asm volatile(
        "mma.sync.aligned.m16n8k16.row.col.f32.f16.f16.f32 "
        "{%0,%1,%2,%3}, {%4,%5,%6,%7}, {%8,%9}, {%0,%1,%2,%3};"
        : "+f"(c[0]), "+f"(c[1]), "+f"(c[2]), "+f"(c[3])
        : "r"(a[0]), "r"(a[1]), "r"(a[2]), "r"(a[3]), "r"(b[0]), "r"(b[1]));
}

// A fragment via ldmatrix.x4: rows base_r..base_r+15, k bytes kb..kb+31
__device__ __forceinline__ void ld_afrag(uint32_t* afr, uint32_t Asu,
                                         int base_r, int kb, int lane) {
    const int row = base_r + (lane & 15);
    ldsm_x4(afr, Asu + SWZB(row * 128 + kb + ((lane >> 4) << 4)));
}
// B fragment pair via ldmatrix.x4: n rows base_n..+15 (two n8 blocks), k bytes kb..kb+31
__device__ __forceinline__ void ld_bfrag2(uint32_t* b4, uint32_t Bsu,
                                          int base_n, int kb, int lane) {
    const int n = base_n + ((lane >> 4) << 3) + (lane & 7);
    const int koff = kb + (((lane >> 3) & 1) << 4);
    ldsm_x4(b4, Bsu + SWZB(n * 128 + koff));
}

// ================== main GEMM: Out[M,NC] = A[M,768]h @ Wt[NC,768]h^T ==================
// Tile 128x128xK64, 256 threads (8 warps = 4m x 2n), 2-stage cp.async, 1 sync/chunk.
template<int NC, bool RELU, bool SPLITB>
__global__ void __launch_bounds__(256, 2) gemm_h(
    const __half* __restrict__ A,
    const __half* __restrict__ Wt,
    const float* __restrict__ bias0,
    const float* __restrict__ bias1,
    const __half* __restrict__ residh,
    __half* __restrict__ OutH)
{
    extern __shared__ char smc[];     // 2 stages x (A 16KB + B 16KB)
    const uint32_t sbase = smem_u32(smc);
    const int tid  = threadIdx.x;
    const int lane = tid & 31;
    const int wid  = tid >> 5;
    const int wm   = wid & 3;
    const int wn   = wid >> 2;
    const int lr   = lane >> 2;
    const int lc   = lane & 3;
    const int bm   = blockIdx.y * 128;
    const int bn   = blockIdx.x * 128;

    float acc[2][8][4];
    #pragma unroll
    for (int i = 0; i < 2; i++)
        #pragma unroll
        for (int j = 0; j < 8; j++)
            #pragma unroll
            for (int k = 0; k < 4; k++) acc[i][j][k] = 0.f;

    const int lrow = tid >> 3;
    const int lc4  = tid & 7;

    auto issue_load = [&](int c, int s) {
        const uint32_t abase = sbase + (uint32_t)s * 32768u;
        const uint32_t bbase = abase + 16384u;
        const int k0 = c * 64;
        #pragma unroll
        for (int i = 0; i < 4; i++) {
            const int row = lrow + i * 32;
            const uint32_t soff = SWZB(row * 128 + lc4 * 16);
            cp16(abase + soff, A  + (size_t)(bm + row) * CC + k0 + lc4 * 8);
            cp16(bbase + soff, Wt + (size_t)(bn + row) * CC + k0 + lc4 * 8);
        }
        CP_COMMIT();
    };

    issue_load(0, 0);

    #pragma unroll 1
    for (int c = 0; c < NCHUNK; c++) {
        CP_WAIT0();
        __syncthreads();
        if (c + 1 < NCHUNK) issue_load(c + 1, (c + 1) & 1);

        const uint32_t Asu = sbase + (uint32_t)(c & 1) * 32768u;
        const uint32_t Bsu = Asu + 16384u;

        #pragma unroll
        for (int ks = 0; ks < 4; ks++) {
            const int kb = ks * 32;
            uint32_t afr[2][4];
            #pragma unroll
            for (int fm = 0; fm < 2; fm++)
                ld_afrag(afr[fm], Asu, wm * 32 + fm * 16, kb, lane);
            uint32_t bfr[4][4];
            #pragma unroll
            for (int fp = 0; fp < 4; fp++)
                ld_bfrag2(bfr[fp], Bsu, wn * 64 + fp * 16, kb, lane);
            #pragma unroll
            for (int fm = 0; fm < 2; fm++)
                #pragma unroll
                for (int fp = 0; fp < 4; fp++) {
                    mma_f16(acc[fm][fp * 2 + 0], afr[fm], &bfr[fp][0]);
                    mma_f16(acc[fm][fp * 2 + 1], afr[fm], &bfr[fp][2]);
                }
        }
    }

    // ---- epilogue ----
    #pragma unroll
    for (int fm = 0; fm < 2; fm++) {
        #pragma unroll
        for (int h = 0; h < 2; h++) {
            const int m = bm + wm * 32 + fm * 16 + lr + h * 8;
            #pragma unroll
            for (int fn = 0; fn < 8; fn++) {
                const int n = bn + wn * 64 + fn * 8 + lc * 2;
                float b0, b1;
                if (SPLITB) {
                    b0 = (n < RR) ? bias0[n] : bias1[n - RR];
                    b1 = (n + 1 < RR) ? bias0[n + 1] : bias1[n + 1 - RR];
                } else {
                    b0 = bias0[n]; b1 = bias0[n + 1];
                }
                float vx = acc[fm][fn][h * 2 + 0] + b0;
                float vy = acc[fm][fn][h * 2 + 1] + b1;
                if (RELU) {
                    const float2 rx = __half22float2(
                        *(const half2*)(residh + (size_t)m * NC + n));
                    vx = fmaxf(vx, 0.f) + rx.x;
                    vy = fmaxf(vy, 0.f) + rx.y;
                }
                *(half2*)(OutH + (size_t)m * NC + n) = __floats2half2_rn(vx, vy);
            }
        }
    }
}

// ================== scores = Q @ K^T / sqrt(R) (fp16 tensor, batched) ==================
// Per batch: M=192 (180 valid), N=96, K=192 (3 chunks of 64). grid (2, 256).
__global__ void __launch_bounds__(256, 1) scores_h() {
    __shared__ __align__(128) char As[192 * 128];   // Q tile [192][64h]
    __shared__ __align__(128) char Bs[96 * 128];    // K tile [96][64h]
    const int tid = threadIdx.x;
    const int wid = tid >> 5, lane = tid & 31;
    const int wm = wid & 3, wn = wid >> 2;
    const int lr = lane >> 2, lc = lane & 3;
    const int b  = blockIdx.y;
    const int bn = blockIdx.x * 96;
    const __half* qb = g_QKh + (size_t)b * NN * 384;
    const uint32_t Asu = smem_u32(As), Bsu = smem_u32(Bs);

    float acc[3][6][4];
    #pragma unroll
    for (int i = 0; i < 3; i++)
        #pragma unroll
        for (int j = 0; j < 6; j++)
            #pragma unroll
            for (int k = 0; k < 4; k++) acc[i][j][k] = 0.f;

    uint4 ar[6], br[3];
    auto gload = [&](int c) {
        const int k0 = c * 64;
        #pragma unroll
        for (int i = 0; i < 6; i++) {
            const int idx = tid + i * 256;
            const int row = idx >> 3, c4 = idx & 7;
            uint4 v = make_uint4(0, 0, 0, 0);
            if (row < NN) v = *(const uint4*)(qb + (size_t)row * 384 + k0 + c4 * 8);
            ar[i] = v;
        }
        #pragma unroll
        for (int i = 0; i < 3; i++) {
            const int idx = tid + i * 256;
            const int row = idx >> 3, c4 = idx & 7;
            uint4 v = make_uint4(0, 0, 0, 0);
            if (bn + row < NN) v = *(const uint4*)(qb + (size_t)(bn + row) * 384 + 192 + k0 + c4 * 8);
            br[i] = v;
        }
    };
    auto sstore = [&]() {
        #pragma unroll
        for (int i = 0; i < 6; i++) {
            const int idx = tid + i * 256;
            const int row = idx >> 3, c4 = idx & 7;
            *(uint4*)(As + SWZB(row * 128 + c4 * 16)) = ar[i];
        }
        #pragma unroll
        for (int i = 0; i < 3; i++) {
            const int idx = tid + i * 256;
            const int row = idx >> 3, c4 = idx & 7;
            *(uint4*)(Bs + SWZB(row * 128 + c4 * 16)) = br[i];
        }
    };

    gload(0);
    #pragma unroll 1
    for (int c = 0; c < 3; c++) {
        sstore();
        if (c < 2) gload(c + 1);
        __syncthreads();
        #pragma unroll
        for (int ks = 0; ks < 4; ks++) {
            const int kb = ks * 32;
            uint32_t afr[3][4];
            #pragma unroll
            for (int fm = 0; fm < 3; fm++)
                ld_afrag(afr[fm], Asu, wm * 48 + fm * 16, kb, lane);
            uint32_t bfr[3][4];
            #pragma unroll
            for (int fp = 0; fp < 3; fp++)
                ld_bfrag2(bfr[fp], Bsu, wn * 48 + fp * 16, kb, lane);
            #pragma unroll
            for (int fm = 0; fm < 3; fm++)
                #pragma unroll
                for (int fp = 0; fp < 3; fp++) {
                    mma_f16(acc[fm][fp * 2 + 0], afr[fm], &bfr[fp][0]);
                    mma_f16(acc[fm][fp * 2 + 1], afr[fm], &bfr[fp][2]);
                }
        }
        __syncthreads();
    }

    const float scale = 0.07216878364870323f;   // 1/sqrt(192)
    float* Sb = g_S + (size_t)b * NN * NN;
    #pragma unroll
    for (int fm = 0; fm < 3; fm++) {
        #pragma unroll
        for (int h = 0; h < 2; h++) {
            const int m = wm * 48 + fm * 16 + lr + h * 8;
            if (m < NN) {
                #pragma unroll
                for (int fn = 0; fn < 6; fn++) {
                    const int n = bn + wn * 48 + fn * 8 + lc * 2;
                    if (n < NN)     Sb[(size_t)m * NN + n]     = acc[fm][fn][h * 2 + 0] * scale;
                    if (n + 1 < NN) Sb[(size_t)m * NN + n + 1] = acc[fm][fn][h * 2 + 1] * scale;
                }
            }
        }
    }
}

// ================== z = A_comb @ x (fp16 tensor, batched) ==================
// Per batch tile: M=192 (180 valid), N=128 channels, K=192 tokens (3 chunks of 64).
// grid (6, 256). (R13-proven full-tile version.)
__global__ void __launch_bounds__(256, 1) aggregate_h() {
    __shared__ __align__(128) char As[192 * 128];   // A_comb [192 rows][64 tok]
    __shared__ __align__(128) char Bs[128 * 128];   // x^T [128 ch][64 tok]
    const int tid = threadIdx.x;
    const int wid = tid >> 5, lane = tid & 31;
    const int wm = wid & 3, wn = wid >> 2;
    const int lr = lane >> 2, lc = lane & 3;
    const int b  = blockIdx.y;
    const int bc = blockIdx.x * 128;
    const __half* Sb = g_Sh + (size_t)b * NN * 192;
    const __half* xb = g_xh + (size_t)b * NN * CC;
    const uint32_t Asu = smem_u32(As), Bsu = smem_u32(Bs);

    float acc[3][8][4];
    #pragma unroll
    for (int i = 0; i < 3; i++)
        #pragma unroll
        for (int j = 0; j < 8; j++)
            #pragma unroll
            for (int k = 0; k < 4; k++) acc[i][j][k] = 0.f;

    uint4 ar[6], bra[2], brb[2];
    auto gload = [&](int c) {
        const int k0 = c * 64;
        #pragma unroll
        for (int i = 0; i < 6; i++) {
            const int idx = tid + i * 256;
            const int row = idx >> 3, c4 = idx & 7;
            uint4 v = make_uint4(0, 0, 0, 0);
            if (row < NN) v = *(const uint4*)(Sb + (size_t)row * 192 + k0 + c4 * 8);
            ar[i] = v;
        }
        #pragma unroll
        for (int i = 0; i < 2; i++) {
            const int task = tid + i * 256;
            const int tp = task & 31, chg = task >> 5;
            const int tokA = k0 + 2 * tp, tokB = tokA + 1;
            uint4 va = make_uint4(0, 0, 0, 0), vb = make_uint4(0, 0, 0, 0);
            if (tokA < NN) va = *(const uint4*)(xb + (size_t)tokA * CC + bc + chg * 8);
            if (tokB < NN) vb = *(const uint4*)(xb + (size_t)tokB * CC + bc + chg * 8);
            bra[i] = va; brb[i] = vb;
        }
    };
    auto sstore = [&]() {
        #pragma unroll
        for (int i = 0; i < 6; i++) {
            const int idx = tid + i * 256;
            const int row = idx >> 3, c4 = idx & 7;
            *(uint4*)(As + SWZB(row * 128 + c4 * 16)) = ar[i];
        }
        #pragma unroll
        for (int i = 0; i < 2; i++) {
            const int task = tid + i * 256;
            const int tp = task & 31, chg = task >> 5;
            const ushort* ha = (const ushort*)&bra[i];
            const ushort* hb = (const ushort*)&brb[i];
            #pragma unroll
            for (int j = 0; j < 8; j++) {
                const uint32_t pv = (uint32_t)ha[j] | ((uint32_t)hb[j] << 16);
                *(uint32_t*)(Bs + SWZB((chg * 8 + j) * 128 + tp * 4)) = pv;
            }
        }
    };

    gload(0);
    #pragma unroll 1
    for (int c = 0; c < 3; c++) {
        sstore();
        if (c < 2) gload(c + 1);
        __syncthreads();
        #pragma unroll
        for (int ks = 0; ks < 4; ks++) {
            const int kb = ks * 32;
            uint32_t afr[3][4];
            #pragma unroll
            for (int fm = 0; fm < 3; fm++)
                ld_afrag(afr[fm], Asu, wm * 48 + fm * 16, kb, lane);
            uint32_t bfr[4][4];
            #pragma unroll
            for (int fp = 0; fp < 4; fp++)
                ld_bfrag2(bfr[fp], Bsu, wn * 64 + fp * 16, kb, lane);
            #pragma unroll
            for (int fm = 0; fm < 3; fm++)
                #pragma unroll
                for (int fp = 0; fp < 4; fp++) {
                    mma_f16(acc[fm][fp * 2 + 0], afr[fm], &bfr[fp][0]);
                    mma_f16(acc[fm][fp * 2 + 1], afr[fm], &bfr[fp][2]);
                }
        }
        __syncthreads();
    }

    #pragma unroll
    for (int fm = 0; fm < 3; fm++) {
        #pragma unroll
        for (int h = 0; h < 2; h++) {
            const int m = wm * 48 + fm * 16 + lr + h * 8;
            if (m < NN) {
                #pragma unroll
                for (int fn = 0; fn < 8; fn++) {
                    const int n = bc + wn * 64 + fn * 8 + lc * 2;
                    *(half2*)(g_Zh + ((size_t)b * NN + m) * CC + n) =
                        __floats2half2_rn(acc[fm][fn][h * 2 + 0], acc[fm][fn][h * 2 + 1]);
                }
            }
        }
    }
}

// ---------------- conversion / pack kernels ----------------
__global__ void cvt_x(const float* __restrict__ x) {
    const size_t i = ((size_t)blockIdx.x * 256 + threadIdx.x) * 8;
    const float4 v0 = *(const float4*)(x + i);
    const float4 v1 = *(const float4*)(x + i + 4);
    __half2 o[4];
    o[0] = __floats2half2_rn(v0.x, v0.y);
    o[1] = __floats2half2_rn(v0.z, v0.w);
    o[2] = __floats2half2_rn(v1.x, v1.y);
    o[3] = __floats2half2_rn(v1.z, v1.w);
    *(uint4*)(g_xh + i) = *(const uint4*)o;
}

__global__ void pack_wqk(const float* __restrict__ Wq, const float* __restrict__ Wk) {
    __shared__ float t[32][33];
    int k0 = blockIdx.x * 32, n0 = blockIdx.y * 32, z = blockIdx.z;
    const float* W = z ? Wk : Wq;
    int tx = threadIdx.x, ty = threadIdx.y;
    t[ty][tx] = W[(size_t)(k0 + ty) * RR + n0 + tx];
    __syncthreads();
    g_Wqkth[(size_t)(z * RR + n0 + ty) * CC + k0 + tx] = __float2half_rn(t[tx][ty]);
}

__global__ void pack_wg(const float* __restrict__ Wg) {
    __shared__ float t[32][33];
    int k0 = blockIdx.x * 32, n0 = blockIdx.y * 32;
    int tx = threadIdx.x, ty = threadIdx.y;
    t[ty][tx] = Wg[(size_t)(k0 + ty) * CC + n0 + tx];
    __syncthreads();
    g_Wgth[(size_t)(n0 + ty) * CC + k0 + tx] = __float2half_rn(t[tx][ty]);
}

// ---------------- softmax + combine: warp-per-row, f32 scores -> fp16 A_comb ----------------
__global__ void __launch_bounds__(256) softmax_combine(const float* __restrict__ alpha,
                                                       const float* __restrict__ A_phys) {
    const int wid = threadIdx.x >> 5, lane = threadIdx.x & 31;
    const int row = blockIdx.x * 8 + wid;   // global row in [0, MM)
    const int b = row / NN, n = row - b * NN;
    const float* Srow = g_S + (size_t)(b * NN + n) * NN;
    __half* Drow = g_Sh + (size_t)(b * NN + n) * 192;

    float v[6];
    #pragma unroll
    for (int j = 0; j < 6; j++) {
        const int t = lane + j * 32;
        v[j] = (t < NN) ? Srow[t] : -3.0e38f;
    }
    float mx = v[0];
    #pragma unroll
    for (int j = 1; j < 6; j++) mx = fmaxf(mx, v[j]);
    #pragma unroll
    for (int o = 16; o > 0; o >>= 1) mx = fmaxf(mx, __shfl_xor_sync(0xffffffff, mx, o));

    float e[6], s = 0.f;
    #pragma unroll
    for (int j = 0; j < 6; j++) {
        const int t = lane + j * 32;
        e[j] = (t < NN) ? expf(v[j] - mx) : 0.f;
        s += e[j];
    }
    #pragma unroll
    for (int o = 16; o > 0; o >>= 1) s += __shfl_xor_sync(0xffffffff, s, o);

    const float a = 1.f / (1.f + expf(-alpha[0]));
    const float inv = (1.f - a) / s;
    #pragma unroll
    for (int j = 0; j < 6; j++) {
        const int t = lane + j * 32;
        float outv = 0.f;
        if (t < NN) outv = a * A_phys[n * NN + t] + e[j] * inv;
        Drow[t] = __float2half_rn(outv);
    }
}

// ---------------- LayerNorm: warp-per-row (fp16 in, fp32 out) ----------------
__global__ void __launch_bounds__(256) ln_kernel(const float* __restrict__ gamma,
                                                 const float* __restrict__ beta,
                                                 float* __restrict__ out) {
    const int wid = threadIdx.x >> 5, lane = threadIdx.x & 31;
    const size_t row = (size_t)blockIdx.x * 8 + wid;
    const __half* hp = g_Hh + row * CC;

    uint4 raw[3];
    float v[3][8];
    float s = 0.f, sq = 0.f;
    #pragma unroll
    for (int i = 0; i < 3; i++) {
        raw[i] = *(const uint4*)(hp + (i * 32 + lane) * 8);
        const uint32_t* w = (const uint32_t*)&raw[i];
        #pragma unroll
        for (int p = 0; p < 4; p++) {
            const float2 f = __half22float2(*(const half2*)&w[p]);
            v[i][p * 2 + 0] = f.x;
            v[i][p * 2 + 1] = f.y;
            s  += f.x + f.y;
            sq += f.x * f.x + f.y * f.y;
        }
    }
    #pragma unroll
    for (int o = 16; o > 0; o >>= 1) {
        s  += __shfl_xor_sync(0xffffffff, s, o);
        sq += __shfl_xor_sync(0xffffffff, sq, o);
    }
    const float mu  = s * (1.f / 768.f);
    const float var = sq * (1.f / 768.f) - mu * mu;
    const float inv = rsqrtf(var + 1e-5f);

    float* op = out + row * CC;
    #pragma unroll
    for (int i = 0; i < 3; i++) {
        const int e0 = (i * 32 + lane) * 8;
        #pragma unroll
        for (int q = 0; q < 2; q++) {
            const float4 g  = *(const float4*)(gamma + e0 + q * 4);
            const float4 be = *(const float4*)(beta  + e0 + q * 4);
            float4 o4;
            o4.x = (v[i][q * 4 + 0] - mu) * inv * g.x + be.x;
            o4.y = (v[i][q * 4 + 1] - mu) * inv * g.y + be.y;
            o4.z = (v[i][q * 4 + 2] - mu) * inv * g.z + be.z;
            o4.w = (v[i][q * 4 + 3] - mu) * inv * g.w + be.w;
            *(float4*)(op + e0 + q * 4) = o4;
        }
    }
}

// ---------------- host launcher ----------------
#define GEMM_SMEM 65536

extern "C" void kernel_launch(void* const* d_in, const int* in_sizes, int n_in,
                              void* d_out, int out_size) {
    const float* x     = (const float*)d_in[0];
    const float* Wq    = (const float*)d_in[1];
    const float* bq    = (const float*)d_in[2];
    const float* Wk    = (const float*)d_in[3];
    const float* bk    = (const float*)d_in[4];
    const float* Wg    = (const float*)d_in[5];
    const float* bg    = (const float*)d_in[6];
    const float* gamma = (const float*)d_in[7];
    const float* beta  = (const float*)d_in[8];
    const float* alpha = (const float*)d_in[9];
    const float* A_phys= (const float*)d_in[10];
    float* out = (float*)d_out;

    cudaFuncSetAttribute(gemm_h<384, false, true>, cudaFuncAttributeMaxDynamicSharedMemorySize, GEMM_SMEM);
    cudaFuncSetAttribute(gemm_h<768, true, false>, cudaFuncAttributeMaxDynamicSharedMemorySize, GEMM_SMEM);

    void *xh, *wqkt, *wgt, *qk, *zh, *hh;
    cudaGetSymbolAddress(&xh,   g_xh);
    cudaGetSymbolAddress(&wqkt, g_Wqkth);
    cudaGetSymbolAddress(&wgt,  g_Wgth);
    cudaGetSymbolAddress(&qk,   g_QKh);
    cudaGetSymbolAddress(&zh,   g_Zh);
    cudaGetSymbolAddress(&hh,   g_Hh);

    dim3 b32(32, 32);
    cvt_x<<<17280, 256>>>(x);
    pack_wqk<<<dim3(24, 6, 2), b32>>>(Wq, Wk);
    pack_wg<<<dim3(24, 24), b32>>>(Wg);

    gemm_h<384, false, true><<<dim3(3, 360), 256, GEMM_SMEM>>>(
        (const __half*)xh, (const __half*)wqkt, bq, bk, nullptr, (__half*)qk);
    scores_h<<<dim3(2, 256), 256>>>();
    softmax_combine<<<MM / 8, 256>>>(alpha, A_phys);
    aggregate_h<<<dim3(6, 256), 256>>>();
    gemm_h<768, true, false><<<dim3(6, 360), 256, GEMM_SMEM>>>(
        (const __half*)zh, (const __half*)wgt, bg, nullptr,
        (const __half*)xh, (__half*)hh);
    ln_kernel<<<MM / 8, 256>>>(gamma, beta, out);
}

// round 17
// speedup vs baseline: 1.0424x; 1.0144x over previous
#include <cuda_runtime.h>
#include <cuda_fp16.h>
#include <math.h>
#include <stdint.h>

#define BB 256
#define NN 180
#define CC 768
#define RR 192
#define MM (BB*NN)     // 46080
#define NCHUNK (CC/64) // 12 K-chunks of 64 halfs (128B)

// ---------------- scratch (static device allocations) ----------------
__device__ __half g_xh[(size_t)MM * CC];       // fp16 copy of x
__device__ __half g_Wqkth[384 * 768];          // [n][k] fp16 Wq^T | Wk^T
__device__ __half g_Wgth[768 * 768];           // [n][k] fp16 Wg^T
__device__ __half g_QKh[(size_t)MM * 384];     // [M, 384] Q|K fp16
__device__ float  g_S[(size_t)BB * NN * NN];   // raw scores f32
__device__ __half g_Sh[(size_t)BB * NN * 192]; // A_comb fp16, rows padded to 192
__device__ __half g_Zh[(size_t)MM * CC];       // A_comb @ x, fp16
__device__ __half g_Hh[(size_t)MM * CC];       // pre-LN h, fp16

// ---------------- helpers ----------------
__device__ __forceinline__ uint32_t smem_u32(const void* p) {
    uint32_t a;
    asm("{ .reg .u64 t; cvta.to.shared.u64 t, %1; cvt.u32.u64 %0, t; }" : "=r"(a) : "l"(p));
    return a;
}
// 128-byte swizzle on byte offsets (rows are 128B)
#define SWZB(o) ((o) ^ (((o) >> 3) & 0x70))

__device__ __forceinline__ void cp16(uint32_t dst, const void* src) {
    asm volatile("cp.async.ca.shared.global [%0], [%1], 16;"
                 :: "r"(dst), "l"(src) : "memory");
}
#define CP_COMMIT() asm volatile("cp.async.commit_group;" ::: "memory")
#define CP_WAIT1()  asm volatile("cp.async.wait_group 1;" ::: "memory")
#define CP_WAIT0()  asm volatile("cp.async.wait_group 0;" ::: "memory")

__device__ __forceinline__ void ldsm_x4(uint32_t* r, uint32_t addr) {
    asm volatile("ldmatrix.sync.aligned.m8n8.x4.shared.b16 {%0,%1,%2,%3}, [%4];"
                 : "=r"(r[0]), "=r"(r[1]), "=r"(r[2]), "=r"(r[3]) : "r"(addr));
}

__device__ __forceinline__ void mma_f16(float* c, const uint32_t* a, const uint32_t* b) {
    asm volatile(
        "mma.sync.aligned.m16n8k16.row.col.f32.f16.f16.f32 "
        "{%0,%1,%2,%3}, {%4,%5,%6,%7}, {%8,%9}, {%0,%1,%2,%3};"
        : "+f"(c[0]), "+f"(c[1]), "+f"(c[2]), "+f"(c[3])
        : "r"(a[0]), "r"(a[1]), "r"(a[2]), "r"(a[3]), "r"(b[0]), "r"(b[1]));
}

// A fragment via ldmatrix.x4: rows base_r..base_r+15, k bytes kb..kb+31
__device__ __forceinline__ void ld_afrag(uint32_t* afr, uint32_t Asu,
                                         int base_r, int kb, int lane) {
    const int row = base_r + (lane & 15);
    ldsm_x4(afr, Asu + SWZB(row * 128 + kb + ((lane >> 4) << 4)));
}
// B fragment pair via ldmatrix.x4: n rows base_n..+15 (two n8 blocks), k bytes kb..kb+31
__device__ __forceinline__ void ld_bfrag2(uint32_t* b4, uint32_t Bsu,
                                          int base_n, int kb, int lane) {
    const int n = base_n + ((lane >> 4) << 3) + (lane & 7);
    const int koff = kb + (((lane >> 3) & 1) << 4);
    ldsm_x4(b4, Bsu + SWZB(n * 128 + koff));
}

// ================== main GEMM: Out[M,NC] = A[M,768]h @ Wt[NC,768]h^T ==================
// Tile 128x128xK64, 256 threads (8 warps = 4m x 2n), 2-stage cp.async, 1 sync/chunk.
template<int NC, bool RELU, bool SPLITB>
__global__ void __launch_bounds__(256, 2) gemm_h(
    const __half* __restrict__ A,
    const __half* __restrict__ Wt,
    const float* __restrict__ bias0,
    const float* __restrict__ bias1,
    const __half* __restrict__ residh,
    __half* __restrict__ OutH)
{
    extern __shared__ char smc[];     // 2 stages x (A 16KB + B 16KB)
    const uint32_t sbase = smem_u32(smc);
    const int tid  = threadIdx.x;
    const int lane = tid & 31;
    const int wid  = tid >> 5;
    const int wm   = wid & 3;
    const int wn   = wid >> 2;
    const int lr   = lane >> 2;
    const int lc   = lane & 3;
    const int bm   = blockIdx.y * 128;
    const int bn   = blockIdx.x * 128;

    float acc[2][8][4];
    #pragma unroll
    for (int i = 0; i < 2; i++)
        #pragma unroll
        for (int j = 0; j < 8; j++)
            #pragma unroll
            for (int k = 0; k < 4; k++) acc[i][j][k] = 0.f;

    const int lrow = tid >> 3;
    const int lc4  = tid & 7;

    auto issue_load = [&](int c, int s) {
        const uint32_t abase = sbase + (uint32_t)s * 32768u;
        const uint32_t bbase = abase + 16384u;
        const int k0 = c * 64;
        #pragma unroll
        for (int i = 0; i < 4; i++) {
            const int row = lrow + i * 32;
            const uint32_t soff = SWZB(row * 128 + lc4 * 16);
            cp16(abase + soff, A  + (size_t)(bm + row) * CC + k0 + lc4 * 8);
            cp16(bbase + soff, Wt + (size_t)(bn + row) * CC + k0 + lc4 * 8);
        }
        CP_COMMIT();
    };

    issue_load(0, 0);

    #pragma unroll 1
    for (int c = 0; c < NCHUNK; c++) {
        CP_WAIT0();
        __syncthreads();
        if (c + 1 < NCHUNK) issue_load(c + 1, (c + 1) & 1);

        const uint32_t Asu = sbase + (uint32_t)(c & 1) * 32768u;
        const uint32_t Bsu = Asu + 16384u;

        #pragma unroll
        for (int ks = 0; ks < 4; ks++) {
            const int kb = ks * 32;
            uint32_t afr[2][4];
            #pragma unroll
            for (int fm = 0; fm < 2; fm++)
                ld_afrag(afr[fm], Asu, wm * 32 + fm * 16, kb, lane);
            uint32_t bfr[4][4];
            #pragma unroll
            for (int fp = 0; fp < 4; fp++)
                ld_bfrag2(bfr[fp], Bsu, wn * 64 + fp * 16, kb, lane);
            #pragma unroll
            for (int fm = 0; fm < 2; fm++)
                #pragma unroll
                for (int fp = 0; fp < 4; fp++) {
                    mma_f16(acc[fm][fp * 2 + 0], afr[fm], &bfr[fp][0]);
                    mma_f16(acc[fm][fp * 2 + 1], afr[fm], &bfr[fp][2]);
                }
        }
    }

    // ---- epilogue ----
    #pragma unroll
    for (int fm = 0; fm < 2; fm++) {
        #pragma unroll
        for (int h = 0; h < 2; h++) {
            const int m = bm + wm * 32 + fm * 16 + lr + h * 8;
            #pragma unroll
            for (int fn = 0; fn < 8; fn++) {
                const int n = bn + wn * 64 + fn * 8 + lc * 2;
                float b0, b1;
                if (SPLITB) {
                    b0 = (n < RR) ? bias0[n] : bias1[n - RR];
                    b1 = (n + 1 < RR) ? bias0[n + 1] : bias1[n + 1 - RR];
                } else {
                    b0 = bias0[n]; b1 = bias0[n + 1];
                }
                float vx = acc[fm][fn][h * 2 + 0] + b0;
                float vy = acc[fm][fn][h * 2 + 1] + b1;
                if (RELU) {
                    const float2 rx = __half22float2(
                        *(const half2*)(residh + (size_t)m * NC + n));
                    vx = fmaxf(vx, 0.f) + rx.x;
                    vy = fmaxf(vy, 0.f) + rx.y;
                }
                *(half2*)(OutH + (size_t)m * NC + n) = __floats2half2_rn(vx, vy);
            }
        }
    }
}

// ================== scores = Q @ K^T / sqrt(R) (fp16 tensor, batched) ==================
// Per batch: M=192 (180 valid), N=96, K=192 (3 chunks of 64). grid (2, 256).
__global__ void __launch_bounds__(256, 1) scores_h() {
    __shared__ __align__(128) char As[192 * 128];   // Q tile [192][64h]
    __shared__ __align__(128) char Bs[96 * 128];    // K tile [96][64h]
    const int tid = threadIdx.x;
    const int wid = tid >> 5, lane = tid & 31;
    const int wm = wid & 3, wn = wid >> 2;
    const int lr = lane >> 2, lc = lane & 3;
    const int b  = blockIdx.y;
    const int bn = blockIdx.x * 96;
    const __half* qb = g_QKh + (size_t)b * NN * 384;
    const uint32_t Asu = smem_u32(As), Bsu = smem_u32(Bs);

    float acc[3][6][4];
    #pragma unroll
    for (int i = 0; i < 3; i++)
        #pragma unroll
        for (int j = 0; j < 6; j++)
            #pragma unroll
            for (int k = 0; k < 4; k++) acc[i][j][k] = 0.f;

    uint4 ar[6], br[3];
    auto gload = [&](int c) {
        const int k0 = c * 64;
        #pragma unroll
        for (int i = 0; i < 6; i++) {
            const int idx = tid + i * 256;
            const int row = idx >> 3, c4 = idx & 7;
            uint4 v = make_uint4(0, 0, 0, 0);
            if (row < NN) v = *(const uint4*)(qb + (size_t)row * 384 + k0 + c4 * 8);
            ar[i] = v;
        }
        #pragma unroll
        for (int i = 0; i < 3; i++) {
            const int idx = tid + i * 256;
            const int row = idx >> 3, c4 = idx & 7;
            uint4 v = make_uint4(0, 0, 0, 0);
            if (bn + row < NN) v = *(const uint4*)(qb + (size_t)(bn + row) * 384 + 192 + k0 + c4 * 8);
            br[i] = v;
        }
    };
    auto sstore = [&]() {
        #pragma unroll
        for (int i = 0; i < 6; i++) {
            const int idx = tid + i * 256;
            const int row = idx >> 3, c4 = idx & 7;
            *(uint4*)(As + SWZB(row * 128 + c4 * 16)) = ar[i];
        }
        #pragma unroll
        for (int i = 0; i < 3; i++) {
            const int idx = tid + i * 256;
            const int row = idx >> 3, c4 = idx & 7;
            *(uint4*)(Bs + SWZB(row * 128 + c4 * 16)) = br[i];
        }
    };

    gload(0);
    #pragma unroll 1
    for (int c = 0; c < 3; c++) {
        sstore();
        if (c < 2) gload(c + 1);
        __syncthreads();
        #pragma unroll
        for (int ks = 0; ks < 4; ks++) {
            const int kb = ks * 32;
            uint32_t afr[3][4];
            #pragma unroll
            for (int fm = 0; fm < 3; fm++)
                ld_afrag(afr[fm], Asu, wm * 48 + fm * 16, kb, lane);
            uint32_t bfr[3][4];
            #pragma unroll
            for (int fp = 0; fp < 3; fp++)
                ld_bfrag2(bfr[fp], Bsu, wn * 48 + fp * 16, kb, lane);
            #pragma unroll
            for (int fm = 0; fm < 3; fm++)
                #pragma unroll
                for (int fp = 0; fp < 3; fp++) {
                    mma_f16(acc[fm][fp * 2 + 0], afr[fm], &bfr[fp][0]);
                    mma_f16(acc[fm][fp * 2 + 1], afr[fm], &bfr[fp][2]);
                }
        }
        __syncthreads();
    }

    const float scale = 0.07216878364870323f;   // 1/sqrt(192)
    float* Sb = g_S + (size_t)b * NN * NN;
    #pragma unroll
    for (int fm = 0; fm < 3; fm++) {
        #pragma unroll
        for (int h = 0; h < 2; h++) {
            const int m = wm * 48 + fm * 16 + lr + h * 8;
            if (m < NN) {
                #pragma unroll
                for (int fn = 0; fn < 6; fn++) {
                    const int n = bn + wn * 48 + fn * 8 + lc * 2;   // always even
                    if (n < NN) {
                        *(float2*)(Sb + (size_t)m * NN + n) =
                            make_float2(acc[fm][fn][h * 2 + 0] * scale,
                                        acc[fm][fn][h * 2 + 1] * scale);
                    }
                }
            }
        }
    }
}

// ================== z = A_comb @ x (fp16 tensor, batched) ==================
// Per batch tile: M=192 (180 valid), N=128 channels, K=192 tokens (3 chunks of 64).
// grid (6, 256). (R13-proven full-tile version.)
__global__ void __launch_bounds__(256, 1) aggregate_h() {
    __shared__ __align__(128) char As[192 * 128];   // A_comb [192 rows][64 tok]
    __shared__ __align__(128) char Bs[128 * 128];   // x^T [128 ch][64 tok]
    const int tid = threadIdx.x;
    const int wid = tid >> 5, lane = tid & 31;
    const int wm = wid & 3, wn = wid >> 2;
    const int lr = lane >> 2, lc = lane & 3;
    const int b  = blockIdx.y;
    const int bc = blockIdx.x * 128;
    const __half* Sb = g_Sh + (size_t)b * NN * 192;
    const __half* xb = g_xh + (size_t)b * NN * CC;
    const uint32_t Asu = smem_u32(As), Bsu = smem_u32(Bs);

    float acc[3][8][4];
    #pragma unroll
    for (int i = 0; i < 3; i++)
        #pragma unroll
        for (int j = 0; j < 8; j++)
            #pragma unroll
            for (int k = 0; k < 4; k++) acc[i][j][k] = 0.f;

    uint4 ar[6], bra[2], brb[2];
    auto gload = [&](int c) {
        const int k0 = c * 64;
        #pragma unroll
        for (int i = 0; i < 6; i++) {
            const int idx = tid + i * 256;
            const int row = idx >> 3, c4 = idx & 7;
            uint4 v = make_uint4(0, 0, 0, 0);
            if (row < NN) v = *(const uint4*)(Sb + (size_t)row * 192 + k0 + c4 * 8);
            ar[i] = v;
        }
        #pragma unroll
        for (int i = 0; i < 2; i++) {
            const int task = tid + i * 256;
            const int tp = task & 31, chg = task >> 5;
            const int tokA = k0 + 2 * tp, tokB = tokA + 1;
            uint4 va = make_uint4(0, 0, 0, 0), vb = make_uint4(0, 0, 0, 0);
            if (tokA < NN) va = *(const uint4*)(xb + (size_t)tokA * CC + bc + chg * 8);
            if (tokB < NN) vb = *(const uint4*)(xb + (size_t)tokB * CC + bc + chg * 8);
            bra[i] = va; brb[i] = vb;
        }
    };
    auto sstore = [&]() {
        #pragma unroll
        for (int i = 0; i < 6; i++) {
            const int idx = tid + i * 256;
            const int row = idx >> 3, c4 = idx & 7;
            *(uint4*)(As + SWZB(row * 128 + c4 * 16)) = ar[i];
        }
        #pragma unroll
        for (int i = 0; i < 2; i++) {
            const int task = tid + i * 256;
            const int tp = task & 31, chg = task >> 5;
            const ushort* ha = (const ushort*)&bra[i];
            const ushort* hb = (const ushort*)&brb[i];
            #pragma unroll
            for (int j = 0; j < 8; j++) {
                const uint32_t pv = (uint32_t)ha[j] | ((uint32_t)hb[j] << 16);
                *(uint32_t*)(Bs + SWZB((chg * 8 + j) * 128 + tp * 4)) = pv;
            }
        }
    };

    gload(0);
    #pragma unroll 1
    for (int c = 0; c < 3; c++) {
        sstore();
        if (c < 2) gload(c + 1);
        __syncthreads();
        #pragma unroll
        for (int ks = 0; ks < 4; ks++) {
            const int kb = ks * 32;
            uint32_t afr[3][4];
            #pragma unroll
            for (int fm = 0; fm < 3; fm++)
                ld_afrag(afr[fm], Asu, wm * 48 + fm * 16, kb, lane);
            uint32_t bfr[4][4];
            #pragma unroll
            for (int fp = 0; fp < 4; fp++)
                ld_bfrag2(bfr[fp], Bsu, wn * 64 + fp * 16, kb, lane);
            #pragma unroll
            for (int fm = 0; fm < 3; fm++)
                #pragma unroll
                for (int fp = 0; fp < 4; fp++) {
                    mma_f16(acc[fm][fp * 2 + 0], afr[fm], &bfr[fp][0]);
                    mma_f16(acc[fm][fp * 2 + 1], afr[fm], &bfr[fp][2]);
                }
        }
        __syncthreads();
    }

    #pragma unroll
    for (int fm = 0; fm < 3; fm++) {
        #pragma unroll
        for (int h = 0; h < 2; h++) {
            const int m = wm * 48 + fm * 16 + lr + h * 8;
            if (m < NN) {
                #pragma unroll
                for (int fn = 0; fn < 8; fn++) {
                    const int n = bc + wn * 64 + fn * 8 + lc * 2;
                    *(half2*)(g_Zh + ((size_t)b * NN + m) * CC + n) =
                        __floats2half2_rn(acc[fm][fn][h * 2 + 0], acc[fm][fn][h * 2 + 1]);
                }
            }
        }
    }
}

// ---------------- conversion / pack kernels ----------------
__global__ void cvt_x(const float* __restrict__ x) {
    const size_t i = ((size_t)blockIdx.x * 256 + threadIdx.x) * 8;
    const float4 v0 = *(const float4*)(x + i);
    const float4 v1 = *(const float4*)(x + i + 4);
    __half2 o[4];
    o[0] = __floats2half2_rn(v0.x, v0.y);
    o[1] = __floats2half2_rn(v0.z, v0.w);
    o[2] = __floats2half2_rn(v1.x, v1.y);
    o[3] = __floats2half2_rn(v1.z, v1.w);
    *(uint4*)(g_xh + i) = *(const uint4*)o;
}

__global__ void pack_wqk(const float* __restrict__ Wq, const float* __restrict__ Wk) {
    __shared__ float t[32][33];
    int k0 = blockIdx.x * 32, n0 = blockIdx.y * 32, z = blockIdx.z;
    const float* W = z ? Wk : Wq;
    int tx = threadIdx.x, ty = threadIdx.y;
    t[ty][tx] = W[(size_t)(k0 + ty) * RR + n0 + tx];
    __syncthreads();
    g_Wqkth[(size_t)(z * RR + n0 + ty) * CC + k0 + tx] = __float2half_rn(t[tx][ty]);
}

__global__ void pack_wg(const float* __restrict__ Wg) {
    __shared__ float t[32][33];
    int k0 = blockIdx.x * 32, n0 = blockIdx.y * 32;
    int tx = threadIdx.x, ty = threadIdx.y;
    t[ty][tx] = Wg[(size_t)(k0 + ty) * CC + n0 + tx];
    __syncthreads();
    g_Wgth[(size_t)(n0 + ty) * CC + k0 + tx] = __float2half_rn(t[tx][ty]);
}

// ---------------- softmax + combine: warp-per-row, fully vectorized ----------------
// Each lane owns element pairs p = lane*2 + j*64, j=0..2 (covers 0..191, guard p<180).
// float2 loads of scores/A_phys, half2 stores of A_comb -> 128B coalesced streams.
__global__ void __launch_bounds__(256) softmax_combine(const float* __restrict__ alpha,
                                                       const float* __restrict__ A_phys) {
    const int wid = threadIdx.x >> 5, lane = threadIdx.x & 31;
    const int row = blockIdx.x * 8 + wid;   // global row in [0, MM)
    const int b = row / NN, n = row - b * NN;
    const float* Srow = g_S + (size_t)(b * NN + n) * NN;
    __half* Drow = g_Sh + (size_t)(b * NN + n) * 192;

    float2 v[3];
    #pragma unroll
    for (int j = 0; j < 3; j++) {
        const int p = lane * 2 + j * 64;
        v[j] = (p < NN) ? *(const float2*)(Srow + p) : make_float2(-3.0e38f, -3.0e38f);
    }
    float mx = fmaxf(fmaxf(fmaxf(v[0].x, v[0].y), fmaxf(v[1].x, v[1].y)),
                     fmaxf(v[2].x, v[2].y));
    #pragma unroll
    for (int o = 16; o > 0; o >>= 1) mx = fmaxf(mx, __shfl_xor_sync(0xffffffff, mx, o));

    float2 e[3];
    float s = 0.f;
    #pragma unroll
    for (int j = 0; j < 3; j++) {
        const int p = lane * 2 + j * 64;
        if (p < NN) {
            e[j].x = expf(v[j].x - mx);
            e[j].y = expf(v[j].y - mx);
        } else {
            e[j].x = 0.f; e[j].y = 0.f;
        }
        s += e[j].x + e[j].y;
    }
    #pragma unroll
    for (int o = 16; o > 0; o >>= 1) s += __shfl_xor_sync(0xffffffff, s, o);

    const float a = 1.f / (1.f + expf(-alpha[0]));
    const float inv = (1.f - a) / s;
    #pragma unroll
    for (int j = 0; j < 3; j++) {
        const int p = lane * 2 + j * 64;
        float ox = 0.f, oy = 0.f;
        if (p < NN) {
            const float2 ap = *(const float2*)(A_phys + n * NN + p);
            ox = a * ap.x + e[j].x * inv;
            oy = a * ap.y + e[j].y * inv;
        }
        *(half2*)(Drow + p) = __floats2half2_rn(ox, oy);
    }
}

// ---------------- LayerNorm: warp-per-row (fp16 in, fp32 out) ----------------
__global__ void __launch_bounds__(256) ln_kernel(const float* __restrict__ gamma,
                                                 const float* __restrict__ beta,
                                                 float* __restrict__ out) {
    const int wid = threadIdx.x >> 5, lane = threadIdx.x & 31;
    const size_t row = (size_t)blockIdx.x * 8 + wid;
    const __half* hp = g_Hh + row * CC;

    uint4 raw[3];
    float v[3][8];
    float s = 0.f, sq = 0.f;
    #pragma unroll
    for (int i = 0; i < 3; i++) {
        raw[i] = *(const uint4*)(hp + (i * 32 + lane) * 8);
        const uint32_t* w = (const uint32_t*)&raw[i];
        #pragma unroll
        for (int p = 0; p < 4; p++) {
            const float2 f = __half22float2(*(const half2*)&w[p]);
            v[i][p * 2 + 0] = f.x;
            v[i][p * 2 + 1] = f.y;
            s  += f.x + f.y;
            sq += f.x * f.x + f.y * f.y;
        }
    }
    #pragma unroll
    for (int o = 16; o > 0; o >>= 1) {
        s  += __shfl_xor_sync(0xffffffff, s, o);
        sq += __shfl_xor_sync(0xffffffff, sq, o);
    }
    const float mu  = s * (1.f / 768.f);
    const float var = sq * (1.f / 768.f) - mu * mu;
    const float inv = rsqrtf(var + 1e-5f);

    float* op = out + row * CC;
    #pragma unroll
    for (int i = 0; i < 3; i++) {
        const int e0 = (i * 32 + lane) * 8;
        #pragma unroll
        for (int q = 0; q < 2; q++) {
            const float4 g  = *(const float4*)(gamma + e0 + q * 4);
            const float4 be = *(const float4*)(beta  + e0 + q * 4);
            float4 o4;
            o4.x = (v[i][q * 4 + 0] - mu) * inv * g.x + be.x;
            o4.y = (v[i][q * 4 + 1] - mu) * inv * g.y + be.y;
            o4.z = (v[i][q * 4 + 2] - mu) * inv * g.z + be.z;
            o4.w = (v[i][q * 4 + 3] - mu) * inv * g.w + be.w;
            *(float4*)(op + e0 + q * 4) = o4;
        }
    }
}

// ---------------- host launcher ----------------
#define GEMM_SMEM 65536

extern "C" void kernel_launch(void* const* d_in, const int* in_sizes, int n_in,
                              void* d_out, int out_size) {
    const float* x     = (const float*)d_in[0];
    const float* Wq    = (const float*)d_in[1];
    const float* bq    = (const float*)d_in[2];
    const float* Wk    = (const float*)d_in[3];
    const float* bk    = (const float*)d_in[4];
    const float* Wg    = (const float*)d_in[5];
    const float* bg    = (const float*)d_in[6];
    const float* gamma = (const float*)d_in[7];
    const float* beta  = (const float*)d_in[8];
    const float* alpha = (const float*)d_in[9];
    const float* A_phys= (const float*)d_in[10];
    float* out = (float*)d_out;

    cudaFuncSetAttribute(gemm_h<384, false, true>, cudaFuncAttributeMaxDynamicSharedMemorySize, GEMM_SMEM);
    cudaFuncSetAttribute(gemm_h<768, true, false>, cudaFuncAttributeMaxDynamicSharedMemorySize, GEMM_SMEM);

    void *xh, *wqkt, *wgt, *qk, *zh, *hh;
    cudaGetSymbolAddress(&xh,   g_xh);
    cudaGetSymbolAddress(&wqkt, g_Wqkth);
    cudaGetSymbolAddress(&wgt,  g_Wgth);
    cudaGetSymbolAddress(&qk,   g_QKh);
    cudaGetSymbolAddress(&zh,   g_Zh);
    cudaGetSymbolAddress(&hh,   g_Hh);

    dim3 b32(32, 32);
    cvt_x<<<17280, 256>>>(x);
    pack_wqk<<<dim3(24, 6, 2), b32>>>(Wq, Wk);
    pack_wg<<<dim3(24, 24), b32>>>(Wg);

    gemm_h<384, false, true><<<dim3(3, 360), 256, GEMM_SMEM>>>(
        (const __half*)xh, (const __half*)wqkt, bq, bk, nullptr, (__half*)qk);
    scores_h<<<dim3(2, 256), 256>>>();
    softmax_combine<<<MM / 8, 256>>>(alpha, A_phys);
    aggregate_h<<<dim3(6, 256), 256>>>();
    gemm_h<768, true, false><<<dim3(6, 360), 256, GEMM_SMEM>>>(
        (const __half*)zh, (const __half*)wgt, bg, nullptr,
        (const __half*)xh, (__half*)hh);
    ln_kernel<<<MM / 8, 256>>>(gamma, beta, out);
}